// round 11
// baseline (speedup 1.0000x reference)
#include <cuda_runtime.h>
#include <cstdint>

// ---------------- problem constants ----------------
namespace {
constexpr int CB  = 4;      // batch
constexpr int CS  = 1024;   // seq
constexpr int CD  = 1280;   // model dim
constexpr int CH  = 16;     // heads
constexpr int CHD = 80;     // head dim
constexpr int CM  = CB * CS;          // 4096 rows
constexpr int CNQKV = 3 * CD;         // 3840

// dense GEMM tiling (CTA 128x128, 8 warps 2mx4n, warp tile 64x32), 3-stage cp.async
constexpr int PAW = 36;                       // smem pitch (u32) per 32-k row
constexpr int SSTG = 128 * PAW + 128 * PAW;   // stage stride in u32 = 9216
constexpr int NSTAGE = 3;
constexpr int GEMM_SMEM = NSTAGE * SSTG * 4;  // 110,592 B  (x2 CTAs = 221KB <= 228KB)

// attention smem pitches (u32 units). All row-major.
constexpr int PQ = 84;   // Qs [64][80]: A-frag bank 20g+t bijective
constexpr int PK2 = 84;  // Ks [64][80]: B-frag bank 20g+t bijective
constexpr int PV = 88;   // Vs [64][80]: B-frag bank 24t+g bijective
constexpr int PP = 68;   // Ps [64][64]: A-frag bank 4g+t bijective
constexpr int ATTN_U32 = 64*PQ + 64*PK2 + 64*PV + 64*PP + 128;  // 20864
constexpr int ATTN_SMEM = ATTN_U32 * 4;   // 83,456 B (x2 = 167KB <= 228KB)
}
#define ATTN_SCALE 0.11180339887498948f  // 80^-0.5

// ---------------- scratch (device globals; no allocs allowed) ----------------
__device__ __align__(16) float    g_q[CB * CH * CS * CHD];    // fp32 (pre-rope)
__device__ __align__(16) float    g_k[CB * CH * CS * CHD];    // fp32 (pre-rope)
__device__ __align__(16) uint32_t g_qp[CB * CH * CS * CHD];   // tf32, roped, *SCALE
__device__ __align__(16) uint32_t g_kp[CB * CH * CS * CHD];   // tf32, roped
__device__ __align__(16) uint32_t g_vp[CB * CH * CS * CHD];   // tf32 (from gemm)
// tf32 pre-converted, k-permuted GEMM operands
__device__ __align__(16) uint32_t g_xp[CM * CD];              // [m][k']
__device__ __align__(16) uint32_t g_ctxp[CM * CD];            // [m][k'] (from attn)
__device__ __align__(16) uint32_t g_wqkvp[CNQKV * CD];        // [n][k'] (transposed)
__device__ __align__(16) uint32_t g_wprojp[CD * CD];          // [n][k']

// ---------------- tf32 helpers ----------------
__device__ __forceinline__ uint32_t f2tf32(float f) {
    uint32_t u;
    asm("cvt.rna.tf32.f32 %0, %1;" : "=r"(u) : "f"(f));
    return u;
}
__device__ __forceinline__ void mma_tf32(float c[4],
                                         uint32_t a0, uint32_t a1, uint32_t a2, uint32_t a3,
                                         uint32_t b0, uint32_t b1) {
    asm volatile(
        "mma.sync.aligned.m16n8k8.row.col.f32.tf32.tf32.f32 "
        "{%0,%1,%2,%3}, {%4,%5,%6,%7}, {%8,%9}, {%0,%1,%2,%3};"
        : "+f"(c[0]), "+f"(c[1]), "+f"(c[2]), "+f"(c[3])
        : "r"(a0), "r"(a1), "r"(a2), "r"(a3), "r"(b0), "r"(b1));
}
__device__ __forceinline__ uint32_t smem_u32(const void* p) {
    uint32_t a;
    asm("{ .reg .u64 t; cvta.to.shared.u64 t, %1; cvt.u32.u64 %0, t; }"
        : "=r"(a) : "l"(p));
    return a;
}
__device__ __forceinline__ void cpasync16(uint32_t dst, const void* src) {
    asm volatile("cp.async.cg.shared.global [%0], [%1], 16;" :: "r"(dst), "l"(src));
}
// k-permutation within each 32-block: k' = (k%4)*8 + k/4
__device__ __forceinline__ int kperm(int k) {
    const int kb = k >> 5, kl = k & 31;
    return kb * 32 + (kl & 3) * 8 + (kl >> 2);
}

// ============================================================================
// Pre-convert kernels (x and weights; ctx is produced permuted by attn).
// ============================================================================
__global__ void __launch_bounds__(256)
permA0(const float* __restrict__ in)
{
    const int i = blockIdx.x * 256 + threadIdx.x;      // output float4 index
    const int m  = i / (CD / 4);
    const int c4 = i - m * (CD / 4);
    const int kb = c4 >> 3, q = c4 & 7;
    const float* src = in + (size_t)m * CD + kb * 32 + 16 * (q & 1) + (q >> 1);
    uint4 o = { f2tf32(src[0]), f2tf32(src[4]), f2tf32(src[8]), f2tf32(src[12]) };
    reinterpret_cast<uint4*>(g_xp)[i] = o;
}

template <int MODE>
__global__ void transB(const float* __restrict__ W)
{
    uint32_t* __restrict__ out = MODE ? g_wprojp : g_wqkvp;
    const int N = MODE ? CD : CNQKV;
    __shared__ float tile[32][33];
    const int tx = threadIdx.x, ty = threadIdx.y;
    const int nb = blockIdx.x, kb = blockIdx.y;
    #pragma unroll
    for (int r = 0; r < 4; r++) {
        const int kl = ty + 8 * r;
        tile[kl][tx] = W[(size_t)(kb * 32 + kl) * N + nb * 32 + tx];
    }
    __syncthreads();
    const int ksrc = ((tx & 7) << 2) + (tx >> 3);   // inverse perm
    #pragma unroll
    for (int r = 0; r < 4; r++) {
        const int nl = ty + 8 * r;
        out[(size_t)(nb * 32 + nl) * CD + kb * 32 + tx] = f2tf32(tile[ksrc][nl]);
    }
}

// ============================================================================
// tf32 mma.sync GEMM v5: C(128x128) = A @ W^T-stored + bias.
// 256 threads (8 warps, 2m x 4n), warp tile 64x32 -> 16 warps/SM at 2 CTAs/SM
// (forced via __launch_bounds__(256,2): 128 regs/thr, accum only 64).
// 3-stage cp.async pipeline, one __syncthreads per chunk.
// MODE 0: scatter q/k fp32 + v tf32.  MODE 1: -> out fp32.
// ============================================================================
template <int MODE>
__global__ void __launch_bounds__(256, 2)
gemm_tc4(const float* __restrict__ bias, float* __restrict__ out, int N)
{
    const uint32_t* __restrict__ Ap = MODE ? g_ctxp : g_xp;
    const uint32_t* __restrict__ Bp = MODE ? g_wprojp : g_wqkvp;
    constexpr int K = CD;

    extern __shared__ uint32_t smu[];
    const uint32_t smbase = smem_u32(smu);

    const int tid  = threadIdx.x;
    const int wid  = tid >> 5;
    const int lane = tid & 31;
    const int g    = lane >> 2;
    const int t    = lane & 3;
    const int wm   = wid & 1;        // 2 m-warps (64 rows each)
    const int wn   = wid >> 1;       // 4 n-warps (32 cols each)
    const int m0   = blockIdx.y * 128;
    const int n0   = blockIdx.x * 128;

    float cf[4][4][4];
    #pragma unroll
    for (int im = 0; im < 4; im++)
        #pragma unroll
        for (int in = 0; in < 4; in++)
            #pragma unroll
            for (int r = 0; r < 4; r++) cf[im][in][r] = 0.f;

    auto issue = [&](int c, int p) {
        const uint32_t abase = smbase + (uint32_t)p * SSTG * 4;
        const uint32_t bbase = abase + 128 * PAW * 4;
        const int k0 = c * 32;
        #pragma unroll
        for (int i = 0; i < 4; i++) {          // A: 128 rows x 8 segs, 256 thr
            const int s = tid + 256 * i;
            const int m = s >> 3, q = s & 7;
            cpasync16(abase + (uint32_t)(m * PAW + q * 4) * 4,
                      Ap + (size_t)(m0 + m) * K + k0 + q * 4);
        }
        #pragma unroll
        for (int i = 0; i < 4; i++) {          // B: 128 rows x 8 segs
            const int s = tid + 256 * i;
            const int n = s >> 3, q = s & 7;
            cpasync16(bbase + (uint32_t)(n * PAW + q * 4) * 4,
                      Bp + (size_t)(n0 + n) * K + k0 + q * 4);
        }
        asm volatile("cp.async.commit_group;" ::: "memory");
    };

    const int NCH = K / 32;   // 40
    issue(0, 0);
    issue(1, 1);

    for (int c = 0; c < NCH; c++) {
        const int p = c % NSTAGE;
        if (c + 1 < NCH) {
            asm volatile("cp.async.wait_group 1;" ::: "memory");
        } else {
            asm volatile("cp.async.wait_group 0;" ::: "memory");
        }
        __syncthreads();

        if (c + 2 < NCH) issue(c + 2, (c + 2) % NSTAGE);

        const uint32_t* As = smu + p * SSTG;
        const uint32_t* Bs = As + 128 * PAW;

        #pragma unroll
        for (int kh = 0; kh < 2; kh++) {
            uint4 a[4][2], b[4];
            #pragma unroll
            for (int im = 0; im < 4; im++) {
                const int row = wm * 64 + im * 16 + g;
                a[im][0] = *reinterpret_cast<const uint4*>(As + row * PAW + t * 8 + kh * 4);
                a[im][1] = *reinterpret_cast<const uint4*>(As + (row + 8) * PAW + t * 8 + kh * 4);
            }
            #pragma unroll
            for (int in = 0; in < 4; in++) {
                const int n = wn * 32 + in * 8 + g;
                b[in] = *reinterpret_cast<const uint4*>(Bs + n * PAW + t * 8 + kh * 4);
            }
            #pragma unroll
            for (int ks2 = 0; ks2 < 2; ks2++) {
                #pragma unroll
                for (int im = 0; im < 4; im++) {
                    const uint32_t a0 = ks2 ? a[im][0].z : a[im][0].x;
                    const uint32_t a2 = ks2 ? a[im][0].w : a[im][0].y;
                    const uint32_t a1 = ks2 ? a[im][1].z : a[im][1].x;
                    const uint32_t a3 = ks2 ? a[im][1].w : a[im][1].y;
                    #pragma unroll
                    for (int in = 0; in < 4; in++) {
                        const uint32_t b0 = ks2 ? b[in].z : b[in].x;
                        const uint32_t b1 = ks2 ? b[in].w : b[in].y;
                        mma_tf32(cf[im][in], a0, a1, a2, a3, b0, b1);
                    }
                }
            }
        }
    }
    __syncthreads();

    // ---- epilogue: +bias; q/k fp32, v tf32, out fp32 ----
    #pragma unroll
    for (int im = 0; im < 4; im++) {
        #pragma unroll
        for (int in = 0; in < 4; in++) {
            const int mrow0 = m0 + wm * 64 + im * 16 + g;
            const int ncol  = n0 + wn * 32 + in * 8 + 2 * t;
            const float2 bb = *reinterpret_cast<const float2*>(bias + ncol);
            #pragma unroll
            for (int h2 = 0; h2 < 2; h2++) {
                const int m = mrow0 + h2 * 8;
                float2 v;
                v.x = cf[im][in][h2 * 2 + 0] + bb.x;
                v.y = cf[im][in][h2 * 2 + 1] + bb.y;
                if (MODE == 0) {
                    const int b = m >> 10;
                    const int s = m & 1023;
                    const int which = ncol / CD;        // 0=q 1=k 2=v
                    const int r = ncol - which * CD;
                    const int h = r / CHD;
                    const int d = r - h * CHD;
                    const size_t di = ((size_t)(b * CH + h) * CS + s) * CHD + d;
                    if (which == 0)      *reinterpret_cast<float2*>(g_q + di) = v;
                    else if (which == 1) *reinterpret_cast<float2*>(g_k + di) = v;
                    else {
                        uint2 u = { f2tf32(v.x), f2tf32(v.y) };
                        *reinterpret_cast<uint2*>(g_vp + di) = u;
                    }
                } else {
                    *reinterpret_cast<float2*>(out + (size_t)m * CD + ncol) = v;
                }
            }
        }
    }
}

// ============================================================================
// RoPE: fp32 q/k -> roped tf32 g_qp (pre-scaled), g_kp.
// ============================================================================
__global__ void __launch_bounds__(256)
rope_kernel(const float* __restrict__ cosb, const float* __restrict__ sinb)
{
    const int idx = blockIdx.x * blockDim.x + threadIdx.x;
    constexpr int TOT = CB * CH * CS * (CHD / 2);
    if (idx >= TOT) return;
    const int d  = idx % (CHD / 2);
    const int s  = (idx / (CHD / 2)) % CS;
    const int bh = idx / ((CHD / 2) * CS);

    const float c  = cosb[s * CHD + d];
    const float sn = sinb[s * CHD + d];
    const size_t base = ((size_t)bh * CS + s) * CHD;

    const float q1 = g_q[base + d], q2 = g_q[base + d + 40];
    g_qp[base + d]      = f2tf32((q1 * c - q2 * sn) * ATTN_SCALE);
    g_qp[base + d + 40] = f2tf32((q2 * c + q1 * sn) * ATTN_SCALE);

    const float k1 = g_k[base + d], k2 = g_k[base + d + 40];
    g_kp[base + d]      = f2tf32(k1 * c - k2 * sn);
    g_kp[base + d + 40] = f2tf32(k2 * c + k1 * sn);
}

// ============================================================================
// Fused flash attention, tf32 mma.sync (R10 winner, unchanged).
// ============================================================================
__global__ void __launch_bounds__(256, 2)
attn_tc()
{
    extern __shared__ uint32_t smu[];
    uint32_t* Qs = smu;                       // [64][PQ]
    uint32_t* Ks = Qs + 64 * PQ;              // [64][PK2]
    uint32_t* Vs = Ks + 64 * PK2;             // [64][PV]
    float*    Ps = (float*)(Vs + 64 * PV);    // [64][PP]
    float*    sAlpha = Ps + 64 * PP;          // [64]
    float*    sL     = sAlpha + 64;           // [64]
    const uint32_t smb = smem_u32(smu);
    const uint32_t qb = smb;
    const uint32_t kb = smb + 64 * PQ * 4;
    const uint32_t vb = kb + 64 * PK2 * 4;

    const int tid  = threadIdx.x;
    const int wid  = tid >> 5;
    const int lane = tid & 31;
    const int g    = lane >> 2;
    const int t    = lane & 3;
    const int wm   = wid & 1;
    const int wn   = wid >> 1;
    const int wq   = wid & 3;
    const int wd   = wid >> 2;
    const int srow = tid >> 2;
    const int sseg = tid & 3;

    const int bh = blockIdx.y;
    const int q0 = blockIdx.x * 64;

    const uint32_t* __restrict__ Qg = g_qp + (size_t)bh * CS * CHD;
    const uint32_t* __restrict__ Kg = g_kp + (size_t)bh * CS * CHD;
    const uint32_t* __restrict__ Vg = g_vp + (size_t)bh * CS * CHD;

    #pragma unroll
    for (int i = 0; i < 5; i++) {
        const int c = tid + 256 * i;
        const int row = c / 20, seg = c % 20;
        cpasync16(qb + (uint32_t)(row * PQ + seg * 4) * 4,
                  Qg + (size_t)(q0 + row) * CHD + seg * 4);
    }
    asm volatile("cp.async.commit_group;" ::: "memory");

    float m_ = -1e30f, l_ = 0.f;
    float of[5][4];
    #pragma unroll
    for (int i = 0; i < 5; i++)
        #pragma unroll
        for (int r = 0; r < 4; r++) of[i][r] = 0.f;

    for (int tt = 0; tt < CS; tt += 64) {
        __syncthreads();
        #pragma unroll
        for (int i = 0; i < 5; i++) {
            const int c = tid + 256 * i;
            const int row = c / 20, seg = c % 20;
            cpasync16(kb + (uint32_t)(row * PK2 + seg * 4) * 4,
                      Kg + (size_t)(tt + row) * CHD + seg * 4);
            cpasync16(vb + (uint32_t)(row * PV + seg * 4) * 4,
                      Vg + (size_t)(tt + row) * CHD + seg * 4);
        }
        asm volatile("cp.async.commit_group;" ::: "memory");
        asm volatile("cp.async.wait_group 0;" ::: "memory");
        __syncthreads();

        float sacc[2][2][4];
        #pragma unroll
        for (int im = 0; im < 2; im++)
            #pragma unroll
            for (int in = 0; in < 2; in++)
                #pragma unroll
                for (int r = 0; r < 4; r++) sacc[im][in][r] = 0.f;

        #pragma unroll
        for (int ks = 0; ks < 10; ks++) {
            uint32_t af[2][4], bf[2][2];
            #pragma unroll
            for (int im = 0; im < 2; im++) {
                const int row = wm * 32 + im * 16 + g;
                const int col = ks * 8 + t;
                af[im][0] = Qs[row * PQ + col];
                af[im][1] = Qs[(row + 8) * PQ + col];
                af[im][2] = Qs[row * PQ + col + 4];
                af[im][3] = Qs[(row + 8) * PQ + col + 4];
            }
            #pragma unroll
            for (int in = 0; in < 2; in++) {
                const int n = wn * 16 + in * 8 + g;
                bf[in][0] = Ks[n * PK2 + ks * 8 + t];
                bf[in][1] = Ks[n * PK2 + ks * 8 + t + 4];
            }
            #pragma unroll
            for (int im = 0; im < 2; im++)
                #pragma unroll
                for (int in = 0; in < 2; in++)
                    mma_tf32(sacc[im][in], af[im][0], af[im][1], af[im][2], af[im][3],
                             bf[in][0], bf[in][1]);
        }
        #pragma unroll
        for (int im = 0; im < 2; im++) {
            const int r0 = wm * 32 + im * 16;
            #pragma unroll
            for (int in = 0; in < 2; in++) {
                const int cl = wn * 16 + in * 8 + 2 * t;
                *reinterpret_cast<float2*>(&Ps[(r0 + g) * PP + cl]) =
                    make_float2(sacc[im][in][0], sacc[im][in][1]);
                *reinterpret_cast<float2*>(&Ps[(r0 + g + 8) * PP + cl]) =
                    make_float2(sacc[im][in][2], sacc[im][in][3]);
            }
        }
        __syncthreads();

        {
            float* prow = Ps + srow * PP + sseg * 16;
            float vals[16];
            float mx = -1e30f;
            #pragma unroll
            for (int j = 0; j < 16; j++) { vals[j] = prow[j]; mx = fmaxf(mx, vals[j]); }
            mx = fmaxf(mx, __shfl_xor_sync(0xffffffffu, mx, 1));
            mx = fmaxf(mx, __shfl_xor_sync(0xffffffffu, mx, 2));
            const float mnew  = fmaxf(m_, mx);
            const float alpha = __expf(m_ - mnew);
            float rs = 0.f;
            uint32_t* prow_u = reinterpret_cast<uint32_t*>(prow);
            #pragma unroll
            for (int j = 0; j < 16; j++) {
                const float pj = __expf(vals[j] - mnew);
                rs += pj;
                prow_u[j] = f2tf32(pj);
            }
            rs += __shfl_xor_sync(0xffffffffu, rs, 1);
            rs += __shfl_xor_sync(0xffffffffu, rs, 2);
            l_ = l_ * alpha + rs;
            m_ = mnew;
            if (sseg == 0) sAlpha[srow] = alpha;
        }
        __syncthreads();

        {
            const float aL = sAlpha[wq * 16 + g];
            const float aH = sAlpha[wq * 16 + g + 8];
            #pragma unroll
            for (int in = 0; in < 5; in++) {
                of[in][0] *= aL; of[in][1] *= aL;
                of[in][2] *= aH; of[in][3] *= aH;
            }
            const uint32_t* Pu = reinterpret_cast<const uint32_t*>(Ps);
            #pragma unroll
            for (int ks = 0; ks < 8; ks++) {
                const int row = wq * 16 + g;
                const int col = ks * 8 + t;
                uint32_t a0 = Pu[row * PP + col];
                uint32_t a1 = Pu[(row + 8) * PP + col];
                uint32_t a2 = Pu[row * PP + col + 4];
                uint32_t a3 = Pu[(row + 8) * PP + col + 4];
                #pragma unroll
                for (int in = 0; in < 5; in++) {
                    const int n = wd * 40 + in * 8 + g;
                    const uint32_t b0 = Vs[(ks * 8 + t) * PV + n];
                    const uint32_t b1 = Vs[(ks * 8 + t + 4) * PV + n];
                    mma_tf32(of[in], a0, a1, a2, a3, b0, b1);
                }
            }
        }
    }

    __syncthreads();
    if (sseg == 0) sL[srow] = l_;
    __syncthreads();

    const int b = bh >> 4, h = bh & 15;
    const float invL = 1.f / sL[wq * 16 + g];
    const float invH = 1.f / sL[wq * 16 + g + 8];
    const int rL = q0 + wq * 16 + g;
    const int rH = rL + 8;
    uint32_t* ctxL = g_ctxp + ((size_t)b * CS + rL) * CD;
    uint32_t* ctxH = g_ctxp + ((size_t)b * CS + rH) * CD;
    #pragma unroll
    for (int in = 0; in < 5; in++) {
        const int k0g = h * CHD + wd * 40 + in * 8 + 2 * t;
        const int i0 = kperm(k0g);
        const int i1 = kperm(k0g + 1);
        ctxL[i0] = f2tf32(of[in][0] * invL);
        ctxL[i1] = f2tf32(of[in][1] * invL);
        ctxH[i0] = f2tf32(of[in][2] * invH);
        ctxH[i1] = f2tf32(of[in][3] * invH);
    }
}

// ============================================================================
// launch
// ============================================================================
extern "C" void kernel_launch(void* const* d_in, const int* in_sizes, int n_in,
                              void* d_out, int out_size)
{
    const float* x        = (const float*)d_in[0];
    const float* rope_cos = (const float*)d_in[1];
    const float* rope_sin = (const float*)d_in[2];
    const float* Wqkv     = (const float*)d_in[3];
    const float* bqkv     = (const float*)d_in[4];
    const float* Wproj    = (const float*)d_in[5];
    const float* bproj    = (const float*)d_in[6];
    float* out            = (float*)d_out;

    // 0) pre-convert / permute operands
    permA0<<<CM * CD / 4 / 256, 256>>>(x);
    transB<0><<<dim3(CNQKV / 32, CD / 32), dim3(32, 8)>>>(Wqkv);
    transB<1><<<dim3(CD / 32, CD / 32), dim3(32, 8)>>>(Wproj);

    // 1) QKV projection -> g_q/g_k (fp32), g_vp (tf32)
    cudaFuncSetAttribute(gemm_tc4<0>, cudaFuncAttributeMaxDynamicSharedMemorySize, GEMM_SMEM);
    gemm_tc4<0><<<dim3(CNQKV / 128, CM / 128), 256, GEMM_SMEM>>>(bqkv, nullptr, CNQKV);

    // 2) RoPE -> g_qp (tf32, scaled), g_kp (tf32)
    {
        const int pairs = CB * CH * CS * (CHD / 2);
        rope_kernel<<<(pairs + 255) / 256, 256>>>(rope_cos, rope_sin);
    }

    // 3) fused flash attention -> g_ctxp (tf32, permuted)
    cudaFuncSetAttribute(attn_tc, cudaFuncAttributeMaxDynamicSharedMemorySize, ATTN_SMEM);
    attn_tc<<<dim3(CS / 64, CB * CH), 256, ATTN_SMEM>>>();

    // 4) output projection -> d_out
    cudaFuncSetAttribute(gemm_tc4<1>, cudaFuncAttributeMaxDynamicSharedMemorySize, GEMM_SMEM);
    gemm_tc4<1><<<dim3(CD / 128, CM / 128), 256, GEMM_SMEM>>>(bproj, out, CD);
}

// round 12
// speedup vs baseline: 1.7101x; 1.7101x over previous
#include <cuda_runtime.h>
#include <cuda_fp16.h>
#include <cstdint>

// ---------------- problem constants ----------------
namespace {
constexpr int CB  = 4;      // batch
constexpr int CS  = 1024;   // seq
constexpr int CD  = 1280;   // model dim
constexpr int CH  = 16;     // heads
constexpr int CHD = 80;     // head dim
constexpr int CM  = CB * CS;          // 4096 rows
constexpr int CNQKV = 3 * CD;         // 3840
constexpr int KP  = CD / 2;           // 640 fp16 pairs per row

// dense GEMM (CTA 128x128, 4 warps 2x2, warp tile 64x64), fp16 pairs, 3-stage
constexpr int PAWH  = 16;                      // smem pitch in u32 (16 pairs per 32-k chunk)
constexpr int SSTGH = 128 * PAWH * 2;          // A(2048) + B(2048) u32 = 4096
constexpr int NSTAGE = 3;
constexpr int GEMM_SMEM = NSTAGE * SSTGH * 4;  // 49,152 B

// attention smem (u32 units)
constexpr int PQH = 44;   // Qs [64][40p]: frag bank 12g+t bijective mod 32
constexpr int PKH = 44;   // Ks [64][40p]
constexpr int PVH = 36;   // Vt [80][32p]: bank 4g+t bijective
constexpr int PPF = 68;   // Psf fp32 [64][64]
constexpr int PPH = 36;   // Ph fp16 [64][32p]
constexpr int OQ  = 0;
constexpr int OK  = OQ + 64 * PQH;       // 2816
constexpr int OV  = OK + 64 * PKH;       // 5632
constexpr int OSF = OV + 80 * PVH;       // 8512
constexpr int OPH = OSF + 64 * PPF;      // 12864
constexpr int OAL = OPH + 64 * PPH;      // 15168
constexpr int OL  = OAL + 64;            // 15232
constexpr int ATTN_U32 = OL + 64;        // 15296
constexpr int ATTN_SMEM = ATTN_U32 * 4;  // 61,184 B (x2 CTAs = 122KB)
}
#define ATTN_SCALE 0.11180339887498948f  // 80^-0.5

// ---------------- scratch (device globals; no allocs allowed) ----------------
__device__ __align__(16) float    g_q[CB * CH * CS * CHD];     // fp32 (pre-rope)
__device__ __align__(16) float    g_k[CB * CH * CS * CHD];     // fp32 (pre-rope)
__device__ __align__(16) uint32_t g_qp[CB * CH * CS * (CHD/2)]; // fp16x2, roped, *SCALE
__device__ __align__(16) uint32_t g_kp[CB * CH * CS * (CHD/2)]; // fp16x2, roped
__device__ __align__(16) __half   g_vt[CB * CH * CHD * CS];     // fp16, [b,h,d,s]
// fp16x2 pair-permuted GEMM operands
__device__ __align__(16) uint32_t g_xp[CM * KP];               // [m][p']
__device__ __align__(16) uint32_t g_ctxp[CM * KP];             // [m][p'] (from attn)
__device__ __align__(16) uint32_t g_wqkvp[CNQKV * KP];         // [n][p'] (transposed)
__device__ __align__(16) uint32_t g_wprojp[CD * KP];           // [n][p']

// ---------------- helpers ----------------
__device__ __forceinline__ uint32_t f2h2(float lo, float hi) {
    __half2 h = __floats2half2_rn(lo, hi);
    return *reinterpret_cast<uint32_t*>(&h);
}
__device__ __forceinline__ void mma_f16(float c[4],
                                        uint32_t a0, uint32_t a1, uint32_t a2, uint32_t a3,
                                        uint32_t b0, uint32_t b1) {
    asm volatile(
        "mma.sync.aligned.m16n8k16.row.col.f32.f16.f16.f32 "
        "{%0,%1,%2,%3}, {%4,%5,%6,%7}, {%8,%9}, {%0,%1,%2,%3};"
        : "+f"(c[0]), "+f"(c[1]), "+f"(c[2]), "+f"(c[3])
        : "r"(a0), "r"(a1), "r"(a2), "r"(a3), "r"(b0), "r"(b1));
}
__device__ __forceinline__ uint32_t smem_u32(const void* p) {
    uint32_t a;
    asm("{ .reg .u64 t; cvta.to.shared.u64 t, %1; cvt.u32.u64 %0, t; }"
        : "=r"(a) : "l"(p));
    return a;
}
__device__ __forceinline__ void cpasync16(uint32_t dst, const void* src) {
    asm volatile("cp.async.cg.shared.global [%0], [%1], 16;" :: "r"(dst), "l"(src));
}
// 4x4 pair permutation within each 16-pair block (involution): w' = (w%4)*4 + w/4
__device__ __forceinline__ int pperm(int p) {
    const int b = p & ~15, w = p & 15;
    return b + (w & 3) * 4 + (w >> 2);
}

// ============================================================================
// Pre-convert kernels
// ============================================================================
// x [M][K] fp32 -> g_xp [m][p'] fp16x2 pair-permuted
__global__ void __launch_bounds__(256)
permA0(const float* __restrict__ in)
{
    const int i = blockIdx.x * 256 + threadIdx.x;   // u32 output index
    const int m  = i / KP;
    const int pp = i - m * KP;
    const int pair = pperm(pp);   // involution: source pair
    const float* s = in + (size_t)m * CD + 2 * pair;
    g_xp[i] = f2h2(s[0], s[1]);
}

// W [K][N] fp32 -> [N][p'] fp16x2, transposed + pair-permuted
template <int MODE>
__global__ void transB(const float* __restrict__ W)
{
    uint32_t* __restrict__ out = MODE ? g_wprojp : g_wqkvp;
    const int N = MODE ? CD : CNQKV;
    __shared__ float tile[32][33];
    const int tx = threadIdx.x, ty = threadIdx.y;
    const int tid = ty * 32 + tx;
    const int nb = blockIdx.x, kb = blockIdx.y;
    #pragma unroll
    for (int r = 0; r < 4; r++) {
        const int kl = ty + 8 * r;
        tile[kl][tx] = W[(size_t)(kb * 32 + kl) * N + nb * 32 + tx];
    }
    __syncthreads();
    #pragma unroll
    for (int i = 0; i < 2; i++) {
        const int o = tid + 256 * i;        // 512 outputs: 32 n x 16 pairs
        const int n  = o >> 4;
        const int w1 = o & 15;
        const int w  = (w1 & 3) * 4 + (w1 >> 2);
        out[(size_t)(nb * 32 + n) * KP + kb * 16 + w1] =
            f2h2(tile[2 * w][n], tile[2 * w + 1][n]);
    }
}

// ============================================================================
// fp16 mma.sync GEMM: C(128x128) = A @ W^T-stored + bias.
// 128 threads (4 warps 2x2), warp tile 64x64 (4x8 m16n8k16 atoms).
// 3-stage cp.async, one __syncthreads per chunk (32 k = 16 pairs).
// MODE 0: scatter q/k fp32 + v fp16 [b,h,d,s].  MODE 1: -> out fp32.
// ============================================================================
template <int MODE>
__global__ void __launch_bounds__(128)
gemm_h(const float* __restrict__ bias, float* __restrict__ out, int N)
{
    const uint32_t* __restrict__ Ap = MODE ? g_ctxp : g_xp;
    const uint32_t* __restrict__ Bp = MODE ? g_wprojp : g_wqkvp;

    extern __shared__ uint32_t smu[];
    const uint32_t smbase = smem_u32(smu);

    const int tid  = threadIdx.x;
    const int wid  = tid >> 5;
    const int lane = tid & 31;
    const int g    = lane >> 2;
    const int t    = lane & 3;
    const int wm   = wid & 1;
    const int wn   = wid >> 1;
    const int m0   = blockIdx.y * 128;
    const int n0   = blockIdx.x * 128;

    float cf[4][8][4];
    #pragma unroll
    for (int im = 0; im < 4; im++)
        #pragma unroll
        for (int in = 0; in < 8; in++)
            #pragma unroll
            for (int r = 0; r < 4; r++) cf[im][in][r] = 0.f;

    auto issue = [&](int c, int p) {
        const uint32_t abase = smbase + (uint32_t)p * SSTGH * 4;
        const uint32_t bbase = abase + 128 * PAWH * 4;
        const int p0 = c * 16;
        #pragma unroll
        for (int i = 0; i < 4; i++) {          // A: 128 rows x 4 segs
            const int s = tid + 128 * i;
            const int row = s >> 2, seg = s & 3;
            cpasync16(abase + (uint32_t)(row * PAWH + seg * 4) * 4,
                      Ap + (size_t)(m0 + row) * KP + p0 + seg * 4);
        }
        #pragma unroll
        for (int i = 0; i < 4; i++) {          // B: 128 rows x 4 segs
            const int s = tid + 128 * i;
            const int row = s >> 2, seg = s & 3;
            cpasync16(bbase + (uint32_t)(row * PAWH + seg * 4) * 4,
                      Bp + (size_t)(n0 + row) * KP + p0 + seg * 4);
        }
        asm volatile("cp.async.commit_group;" ::: "memory");
    };

    const int NCH = KP / 16;   // 40
    issue(0, 0);
    issue(1, 1);

    for (int c = 0; c < NCH; c++) {
        const int p = c % NSTAGE;
        if (c + 1 < NCH) {
            asm volatile("cp.async.wait_group 1;" ::: "memory");
        } else {
            asm volatile("cp.async.wait_group 0;" ::: "memory");
        }
        __syncthreads();

        if (c + 2 < NCH) issue(c + 2, (c + 2) % NSTAGE);

        const uint32_t* As = smu + p * SSTGH;
        const uint32_t* Bs = As + 128 * PAWH;

        uint4 a[4][2], b[8];
        #pragma unroll
        for (int im = 0; im < 4; im++) {
            const int row = wm * 64 + im * 16 + g;
            a[im][0] = *reinterpret_cast<const uint4*>(As + row * PAWH + t * 4);
            a[im][1] = *reinterpret_cast<const uint4*>(As + (row + 8) * PAWH + t * 4);
        }
        #pragma unroll
        for (int in = 0; in < 8; in++) {
            const int n = wn * 64 + in * 8 + g;
            b[in] = *reinterpret_cast<const uint4*>(Bs + n * PAWH + t * 4);
        }
        // components (post-perm): [0]=pair t, [1]=t+4, [2]=t+8, [3]=t+12
        #pragma unroll
        for (int ks = 0; ks < 2; ks++) {
            #pragma unroll
            for (int im = 0; im < 4; im++) {
                const uint32_t a0 = ks ? a[im][0].z : a[im][0].x;
                const uint32_t a2 = ks ? a[im][0].w : a[im][0].y;
                const uint32_t a1 = ks ? a[im][1].z : a[im][1].x;
                const uint32_t a3 = ks ? a[im][1].w : a[im][1].y;
                #pragma unroll
                for (int in = 0; in < 8; in++) {
                    const uint32_t b0 = ks ? b[in].z : b[in].x;
                    const uint32_t b1 = ks ? b[in].w : b[in].y;
                    mma_f16(cf[im][in], a0, a1, a2, a3, b0, b1);
                }
            }
        }
    }
    __syncthreads();

    // ---- epilogue: +bias; q/k fp32, v fp16 [b,h,d,s], out fp32 ----
    #pragma unroll
    for (int im = 0; im < 4; im++) {
        #pragma unroll
        for (int in = 0; in < 8; in++) {
            const int mrow0 = m0 + wm * 64 + im * 16 + g;
            const int ncol  = n0 + wn * 64 + in * 8 + 2 * t;
            const float2 bb = *reinterpret_cast<const float2*>(bias + ncol);
            #pragma unroll
            for (int h2 = 0; h2 < 2; h2++) {
                const int m = mrow0 + h2 * 8;
                float2 v;
                v.x = cf[im][in][h2 * 2 + 0] + bb.x;
                v.y = cf[im][in][h2 * 2 + 1] + bb.y;
                if (MODE == 0) {
                    const int b = m >> 10;
                    const int s = m & 1023;
                    const int which = ncol / CD;        // 0=q 1=k 2=v
                    const int r = ncol - which * CD;
                    const int h = r / CHD;
                    const int d = r - h * CHD;
                    if (which == 0) {
                        *reinterpret_cast<float2*>(
                            g_q + ((size_t)(b * CH + h) * CS + s) * CHD + d) = v;
                    } else if (which == 1) {
                        *reinterpret_cast<float2*>(
                            g_k + ((size_t)(b * CH + h) * CS + s) * CHD + d) = v;
                    } else {
                        const size_t vbase = ((size_t)(b * CH + h) * CHD + d) * CS + s;
                        g_vt[vbase]      = __float2half_rn(v.x);
                        g_vt[vbase + CS] = __float2half_rn(v.y);
                    }
                } else {
                    *reinterpret_cast<float2*>(out + (size_t)m * CD + ncol) = v;
                }
            }
        }
    }
}

// ============================================================================
// RoPE: fp32 q/k -> roped fp16x2 g_qp (pre-scaled), g_kp. One thread per pair-j.
// ============================================================================
__global__ void __launch_bounds__(256)
rope_kernel(const float* __restrict__ cosb, const float* __restrict__ sinb)
{
    const int idx = blockIdx.x * blockDim.x + threadIdx.x;
    constexpr int TOT = CB * CH * CS * 20;
    if (idx >= TOT) return;
    const int j  = idx % 20;
    const int s  = (idx / 20) % CS;
    const int bh = idx / (20 * CS);

    const float2 c2 = *reinterpret_cast<const float2*>(cosb + s * CHD + 2 * j);
    const float2 s2 = *reinterpret_cast<const float2*>(sinb + s * CHD + 2 * j);
    const size_t base  = ((size_t)bh * CS + s) * CHD;
    const size_t pbase = ((size_t)bh * CS + s) * (CHD / 2);

    const float2 q1 = *reinterpret_cast<const float2*>(g_q + base + 2 * j);
    const float2 q2 = *reinterpret_cast<const float2*>(g_q + base + 40 + 2 * j);
    g_qp[pbase + j]      = f2h2((q1.x * c2.x - q2.x * s2.x) * ATTN_SCALE,
                                (q1.y * c2.y - q2.y * s2.y) * ATTN_SCALE);
    g_qp[pbase + 20 + j] = f2h2((q2.x * c2.x + q1.x * s2.x) * ATTN_SCALE,
                                (q2.y * c2.y + q1.y * s2.y) * ATTN_SCALE);

    const float2 k1 = *reinterpret_cast<const float2*>(g_k + base + 2 * j);
    const float2 k2 = *reinterpret_cast<const float2*>(g_k + base + 40 + 2 * j);
    g_kp[pbase + j]      = f2h2(k1.x * c2.x - k2.x * s2.x,
                                k1.y * c2.y - k2.y * s2.y);
    g_kp[pbase + 20 + j] = f2h2(k2.x * c2.x + k1.x * s2.x,
                                k2.y * c2.y + k1.y * s2.y);
}

// ============================================================================
// Fused flash attention, fp16 mma.sync m16n8k16.
// grid (S/64, B*H), 256 thr. S: warps 2m x 4n (32x16), 5 k16 steps.
// PV: warps 4q x 2d (16x40), 4 k16 steps. Scores fp32, probs fp16.
// ============================================================================
__global__ void __launch_bounds__(256, 2)
attn_h()
{
    extern __shared__ uint32_t smu[];
    uint32_t* Qs = smu + OQ;                  // [64][PQH] fp16x2
    uint32_t* Ks = smu + OK;                  // [64][PKH]
    uint32_t* Vt = smu + OV;                  // [80 d][PVH] pairs along kv
    float*    Psf = (float*)(smu + OSF);      // [64][PPF] fp32 scores
    uint32_t* Ph  = smu + OPH;                // [64][PPH] fp16x2 probs
    float*    sAlpha = (float*)(smu + OAL);   // [64]
    float*    sL     = (float*)(smu + OL);    // [64]
    const uint32_t smb = smem_u32(smu);
    const uint32_t qb = smb + OQ * 4;
    const uint32_t kb = smb + OK * 4;
    const uint32_t vb = smb + OV * 4;

    const int tid  = threadIdx.x;
    const int wid  = tid >> 5;
    const int lane = tid & 31;
    const int g    = lane >> 2;
    const int t    = lane & 3;
    const int wm   = wid & 1;
    const int wn   = wid >> 1;
    const int wq   = wid & 3;
    const int wd   = wid >> 2;
    const int srow = tid >> 2;
    const int sseg = tid & 3;

    const int bh = blockIdx.y;
    const int q0 = blockIdx.x * 64;

    const uint32_t* __restrict__ Qg = g_qp + (size_t)bh * CS * (CHD / 2);
    const uint32_t* __restrict__ Kg = g_kp + (size_t)bh * CS * (CHD / 2);
    const __half*   __restrict__ Vg = g_vt + (size_t)bh * CHD * CS;

    // Q fill: 64 rows x 10 segs (16B each)
    #pragma unroll
    for (int i = 0; i < 3; i++) {
        const int c = tid + 256 * i;
        if (c < 640) {
            const int row = c / 10, seg = c % 10;
            cpasync16(qb + (uint32_t)(row * PQH + seg * 4) * 4,
                      Qg + (size_t)(q0 + row) * 40 + seg * 4);
        }
    }
    asm volatile("cp.async.commit_group;" ::: "memory");

    float m_ = -1e30f, l_ = 0.f;
    float of[5][4];
    #pragma unroll
    for (int i = 0; i < 5; i++)
        #pragma unroll
        for (int r = 0; r < 4; r++) of[i][r] = 0.f;

    for (int tt = 0; tt < CS; tt += 64) {
        __syncthreads();   // prev PV done reading Vt/Ph
        // K fill: 64 rows x 10 segs; Vt fill: 80 d-rows x 8 segs (32 pairs=128B)
        #pragma unroll
        for (int i = 0; i < 3; i++) {
            const int c = tid + 256 * i;
            if (c < 640) {
                const int row = c / 10, seg = c % 10;
                cpasync16(kb + (uint32_t)(row * PKH + seg * 4) * 4,
                          Kg + (size_t)(tt + row) * 40 + seg * 4);
                const int d = c >> 3, sg = c & 7;
                cpasync16(vb + (uint32_t)(d * PVH + sg * 4) * 4,
                          Vg + (size_t)d * CS + tt + sg * 8);
            }
        }
        asm volatile("cp.async.commit_group;" ::: "memory");
        asm volatile("cp.async.wait_group 0;" ::: "memory");
        __syncthreads();

        // ---- S = Q K^T (64x64), warp tile 32x16, 5 k16 steps ----
        float sacc[2][2][4];
        #pragma unroll
        for (int im = 0; im < 2; im++)
            #pragma unroll
            for (int in = 0; in < 2; in++)
                #pragma unroll
                for (int r = 0; r < 4; r++) sacc[im][in][r] = 0.f;

        #pragma unroll
        for (int ks = 0; ks < 5; ks++) {
            uint32_t af[2][4], bf[2][2];
            #pragma unroll
            for (int im = 0; im < 2; im++) {
                const int row = wm * 32 + im * 16 + g;
                const int pc  = ks * 8 + t;
                af[im][0] = Qs[row * PQH + pc];
                af[im][1] = Qs[(row + 8) * PQH + pc];
                af[im][2] = Qs[row * PQH + pc + 4];
                af[im][3] = Qs[(row + 8) * PQH + pc + 4];
            }
            #pragma unroll
            for (int in = 0; in < 2; in++) {
                const int n = wn * 16 + in * 8 + g;
                bf[in][0] = Ks[n * PKH + ks * 8 + t];
                bf[in][1] = Ks[n * PKH + ks * 8 + t + 4];
            }
            #pragma unroll
            for (int im = 0; im < 2; im++)
                #pragma unroll
                for (int in = 0; in < 2; in++)
                    mma_f16(sacc[im][in], af[im][0], af[im][1], af[im][2], af[im][3],
                            bf[in][0], bf[in][1]);
        }
        #pragma unroll
        for (int im = 0; im < 2; im++) {
            const int r0 = wm * 32 + im * 16;
            #pragma unroll
            for (int in = 0; in < 2; in++) {
                const int cl = wn * 16 + in * 8 + 2 * t;
                *reinterpret_cast<float2*>(&Psf[(r0 + g) * PPF + cl]) =
                    make_float2(sacc[im][in][0], sacc[im][in][1]);
                *reinterpret_cast<float2*>(&Psf[(r0 + g + 8) * PPF + cl]) =
                    make_float2(sacc[im][in][2], sacc[im][in][3]);
            }
        }
        __syncthreads();

        // ---- online softmax: fp32 scores -> fp16 probs ----
        {
            const float* prow = Psf + srow * PPF + sseg * 16;
            float vals[16];
            float mx = -1e30f;
            #pragma unroll
            for (int j = 0; j < 16; j++) { vals[j] = prow[j]; mx = fmaxf(mx, vals[j]); }
            mx = fmaxf(mx, __shfl_xor_sync(0xffffffffu, mx, 1));
            mx = fmaxf(mx, __shfl_xor_sync(0xffffffffu, mx, 2));
            const float mnew  = fmaxf(m_, mx);
            const float alpha = __expf(m_ - mnew);
            float rs = 0.f;
            float pj[16];
            #pragma unroll
            for (int j = 0; j < 16; j++) {
                pj[j] = __expf(vals[j] - mnew);
                rs += pj[j];
            }
            uint32_t* ph = Ph + srow * PPH + sseg * 8;
            #pragma unroll
            for (int j = 0; j < 8; j++)
                ph[j] = f2h2(pj[2 * j], pj[2 * j + 1]);
            rs += __shfl_xor_sync(0xffffffffu, rs, 1);
            rs += __shfl_xor_sync(0xffffffffu, rs, 2);
            l_ = l_ * alpha + rs;
            m_ = mnew;
            if (sseg == 0) sAlpha[srow] = alpha;
        }
        __syncthreads();

        // ---- O = O*alpha + P @ V, warp tile 16x40, 4 k16 steps ----
        {
            const float aL = sAlpha[wq * 16 + g];
            const float aH = sAlpha[wq * 16 + g + 8];
            #pragma unroll
            for (int in = 0; in < 5; in++) {
                of[in][0] *= aL; of[in][1] *= aL;
                of[in][2] *= aH; of[in][3] *= aH;
            }
            #pragma unroll
            for (int ks = 0; ks < 4; ks++) {
                const int row = wq * 16 + g;
                const int pc  = ks * 8 + t;
                const uint32_t a0 = Ph[row * PPH + pc];
                const uint32_t a1 = Ph[(row + 8) * PPH + pc];
                const uint32_t a2 = Ph[row * PPH + pc + 4];
                const uint32_t a3 = Ph[(row + 8) * PPH + pc + 4];
                #pragma unroll
                for (int in = 0; in < 5; in++) {
                    const int n = wd * 40 + in * 8 + g;
                    const uint32_t b0 = Vt[n * PVH + pc];
                    const uint32_t b1 = Vt[n * PVH + pc + 4];
                    mma_f16(of[in], a0, a1, a2, a3, b0, b1);
                }
            }
        }
    }

    // ---- epilogue: write g_ctxp (fp16x2, pair-permuted) ----
    __syncthreads();
    if (sseg == 0) sL[srow] = l_;
    __syncthreads();

    const int b = bh >> 4, h = bh & 15;
    const float invL = 1.f / sL[wq * 16 + g];
    const float invH = 1.f / sL[wq * 16 + g + 8];
    const int rL = q0 + wq * 16 + g;
    const int rH = rL + 8;
    uint32_t* ctxL = g_ctxp + ((size_t)b * CS + rL) * KP;
    uint32_t* ctxH = g_ctxp + ((size_t)b * CS + rH) * KP;
    #pragma unroll
    for (int in = 0; in < 5; in++) {
        const int pairidx = h * 40 + wd * 20 + in * 4 + t;   // k0g/2
        const int ppos = pperm(pairidx);
        ctxL[ppos] = f2h2(of[in][0] * invL, of[in][1] * invL);
        ctxH[ppos] = f2h2(of[in][2] * invH, of[in][3] * invH);
    }
}

// ============================================================================
// launch
// ============================================================================
extern "C" void kernel_launch(void* const* d_in, const int* in_sizes, int n_in,
                              void* d_out, int out_size)
{
    const float* x        = (const float*)d_in[0];
    const float* rope_cos = (const float*)d_in[1];
    const float* rope_sin = (const float*)d_in[2];
    const float* Wqkv     = (const float*)d_in[3];
    const float* bqkv     = (const float*)d_in[4];
    const float* Wproj    = (const float*)d_in[5];
    const float* bproj    = (const float*)d_in[6];
    float* out            = (float*)d_out;

    // 0) pre-convert / permute operands to fp16x2
    permA0<<<CM * KP / 256, 256>>>(x);
    transB<0><<<dim3(CNQKV / 32, CD / 32), dim3(32, 8)>>>(Wqkv);
    transB<1><<<dim3(CD / 32, CD / 32), dim3(32, 8)>>>(Wproj);

    // 1) QKV projection -> g_q/g_k (fp32), g_vt (fp16 [b,h,d,s])
    cudaFuncSetAttribute(gemm_h<0>, cudaFuncAttributeMaxDynamicSharedMemorySize, GEMM_SMEM);
    gemm_h<0><<<dim3(CNQKV / 128, CM / 128), 128, GEMM_SMEM>>>(bqkv, nullptr, CNQKV);

    // 2) RoPE -> g_qp (fp16, scaled), g_kp (fp16)
    {
        const int tot = CB * CH * CS * 20;
        rope_kernel<<<(tot + 255) / 256, 256>>>(rope_cos, rope_sin);
    }

    // 3) fused flash attention -> g_ctxp (fp16, permuted)
    cudaFuncSetAttribute(attn_h, cudaFuncAttributeMaxDynamicSharedMemorySize, ATTN_SMEM);
    attn_h<<<dim3(CS / 64, CB * CH), 256, ATTN_SMEM>>>();

    // 4) output projection -> d_out
    cudaFuncSetAttribute(gemm_h<1>, cudaFuncAttributeMaxDynamicSharedMemorySize, GEMM_SMEM);
    gemm_h<1><<<dim3(CD / 128, CM / 128), 128, GEMM_SMEM>>>(bproj, out, CD);
}

// round 13
// speedup vs baseline: 1.8005x; 1.0529x over previous
#include <cuda_runtime.h>
#include <cuda_fp16.h>
#include <cstdint>

// ---------------- problem constants ----------------
namespace {
constexpr int CB  = 4;      // batch
constexpr int CS  = 1024;   // seq
constexpr int CD  = 1280;   // model dim
constexpr int CH  = 16;     // heads
constexpr int CHD = 80;     // head dim
constexpr int CM  = CB * CS;          // 4096 rows
constexpr int CNQKV = 3 * CD;         // 3840
constexpr int KP  = CD / 2;           // 640 fp16 pairs per row

// dense GEMM (CTA 128x128, 4 warps 2x2, warp tile 64x64), fp16, 3-stage,
// chunk = 32 pairs stored as two 128x16 pitch-16 blocks (conflict-free).
constexpr int BLKU  = 128 * 16;                // u32 per block = 2048
constexpr int SSTG2 = 4 * BLKU;                // A(2 blk) + B(2 blk) = 8192 u32
constexpr int NSTAGE = 3;
constexpr int GEMM_SMEM = NSTAGE * SSTG2 * 4;  // 98,304 B (x2 CTAs = 192KB)

// attention smem (u32 units), K/V double-buffered
constexpr int PQH = 44;   // Qs [64][40p]
constexpr int PKH = 44;   // Ks [64][40p]
constexpr int PVH = 36;   // Vt [80][32p]
constexpr int PPF = 68;   // Psf fp32 [64][64]
constexpr int PPH = 36;   // Ph fp16 [64][32p]
constexpr int OQ   = 0;
constexpr int OK0  = OQ + 64 * PQH;        // 2816
constexpr int OK1  = OK0 + 64 * PKH;       // 5632
constexpr int OV0  = OK1 + 64 * PKH;       // 8448
constexpr int OV1  = OV0 + 80 * PVH;       // 11328
constexpr int OSF  = OV1 + 80 * PVH;       // 14208
constexpr int OPH  = OSF + 64 * PPF;       // 18560
constexpr int OAL  = OPH + 64 * PPH;       // 20864
constexpr int OL   = OAL + 64;             // 20928
constexpr int ATTN_U32 = OL + 64;          // 20992
constexpr int ATTN_SMEM = ATTN_U32 * 4;    // 83,968 B (x2 CTAs = 168KB)
}
#define ATTN_SCALE 0.11180339887498948f  // 80^-0.5

// ---------------- scratch (device globals; no allocs allowed) ----------------
__device__ __align__(16) float    g_q[CB * CH * CS * CHD];      // fp32 (pre-rope)
__device__ __align__(16) float    g_k[CB * CH * CS * CHD];      // fp32 (pre-rope)
__device__ __align__(16) uint32_t g_qp[CB * CH * CS * (CHD/2)]; // fp16x2, roped, *SCALE
__device__ __align__(16) uint32_t g_kp[CB * CH * CS * (CHD/2)]; // fp16x2, roped
__device__ __align__(16) __half   g_vt[CB * CH * CHD * CS];     // fp16, [b,h,d,s]
// fp16x2 pair-permuted GEMM operands
__device__ __align__(16) uint32_t g_xp[CM * KP];               // [m][p']
__device__ __align__(16) uint32_t g_ctxp[CM * KP];             // [m][p'] (from attn)
__device__ __align__(16) uint32_t g_wqkvp[CNQKV * KP];         // [n][p'] (transposed)
__device__ __align__(16) uint32_t g_wprojp[CD * KP];           // [n][p']

// ---------------- helpers ----------------
__device__ __forceinline__ uint32_t f2h2(float lo, float hi) {
    __half2 h = __floats2half2_rn(lo, hi);
    return *reinterpret_cast<uint32_t*>(&h);
}
__device__ __forceinline__ void mma_f16(float c[4],
                                        uint32_t a0, uint32_t a1, uint32_t a2, uint32_t a3,
                                        uint32_t b0, uint32_t b1) {
    asm volatile(
        "mma.sync.aligned.m16n8k16.row.col.f32.f16.f16.f32 "
        "{%0,%1,%2,%3}, {%4,%5,%6,%7}, {%8,%9}, {%0,%1,%2,%3};"
        : "+f"(c[0]), "+f"(c[1]), "+f"(c[2]), "+f"(c[3])
        : "r"(a0), "r"(a1), "r"(a2), "r"(a3), "r"(b0), "r"(b1));
}
__device__ __forceinline__ uint32_t smem_u32(const void* p) {
    uint32_t a;
    asm("{ .reg .u64 t; cvta.to.shared.u64 t, %1; cvt.u32.u64 %0, t; }"
        : "=r"(a) : "l"(p));
    return a;
}
__device__ __forceinline__ void cpasync16(uint32_t dst, const void* src) {
    asm volatile("cp.async.cg.shared.global [%0], [%1], 16;" :: "r"(dst), "l"(src));
}
// 4x4 pair permutation within each 16-pair block (involution): w' = (w%4)*4 + w/4
__device__ __forceinline__ int pperm(int p) {
    const int b = p & ~15, w = p & 15;
    return b + (w & 3) * 4 + (w >> 2);
}

// ============================================================================
// Pre-convert kernels
// ============================================================================
__global__ void __launch_bounds__(256)
permA0(const float* __restrict__ in)
{
    const int i = blockIdx.x * 256 + threadIdx.x;   // u32 output index
    const int m  = i / KP;
    const int pp = i - m * KP;
    const int pair = pperm(pp);
    const float* s = in + (size_t)m * CD + 2 * pair;
    g_xp[i] = f2h2(s[0], s[1]);
}

template <int MODE>
__global__ void transB(const float* __restrict__ W)
{
    uint32_t* __restrict__ out = MODE ? g_wprojp : g_wqkvp;
    const int N = MODE ? CD : CNQKV;
    __shared__ float tile[32][33];
    const int tx = threadIdx.x, ty = threadIdx.y;
    const int tid = ty * 32 + tx;
    const int nb = blockIdx.x, kb = blockIdx.y;
    #pragma unroll
    for (int r = 0; r < 4; r++) {
        const int kl = ty + 8 * r;
        tile[kl][tx] = W[(size_t)(kb * 32 + kl) * N + nb * 32 + tx];
    }
    __syncthreads();
    #pragma unroll
    for (int i = 0; i < 2; i++) {
        const int o = tid + 256 * i;        // 512 outputs: 32 n x 16 pairs
        const int n  = o >> 4;
        const int w1 = o & 15;
        const int w  = (w1 & 3) * 4 + (w1 >> 2);
        out[(size_t)(nb * 32 + n) * KP + kb * 16 + w1] =
            f2h2(tile[2 * w][n], tile[2 * w + 1][n]);
    }
}

// ============================================================================
// fp16 mma.sync GEMM v2: chunk = 32 pairs (two 128x16 pitch-16 blocks).
// 128 threads (4 warps 2x2), warp tile 64x64. 20 chunks, 3-stage cp.async.
// MODE 0: scatter q/k fp32 + v fp16 [b,h,d,s].  MODE 1: -> out fp32.
// ============================================================================
template <int MODE>
__global__ void __launch_bounds__(128)
gemm_h2(const float* __restrict__ bias, float* __restrict__ out, int N)
{
    const uint32_t* __restrict__ Ap = MODE ? g_ctxp : g_xp;
    const uint32_t* __restrict__ Bp = MODE ? g_wprojp : g_wqkvp;

    extern __shared__ uint32_t smu[];
    const uint32_t smbase = smem_u32(smu);

    const int tid  = threadIdx.x;
    const int wid  = tid >> 5;
    const int lane = tid & 31;
    const int g    = lane >> 2;
    const int t    = lane & 3;
    const int wm   = wid & 1;
    const int wn   = wid >> 1;
    const int m0   = blockIdx.y * 128;
    const int n0   = blockIdx.x * 128;

    float cf[4][8][4];
    #pragma unroll
    for (int im = 0; im < 4; im++)
        #pragma unroll
        for (int in = 0; in < 8; in++)
            #pragma unroll
            for (int r = 0; r < 4; r++) cf[im][in][r] = 0.f;

    auto issue = [&](int c, int p) {
        const uint32_t abase = smbase + (uint32_t)p * SSTG2 * 4;
        const uint32_t bbase = abase + 2 * BLKU * 4;
        const int p0 = c * 32;
        #pragma unroll
        for (int i = 0; i < 8; i++) {          // A: 128 rows x 8 segs
            const int s = tid + 128 * i;
            const int row = s >> 3, seg = s & 7;
            const uint32_t dst = abase +
                (uint32_t)((seg >> 2) * BLKU + row * 16 + (seg & 3) * 4) * 4;
            cpasync16(dst, Ap + (size_t)(m0 + row) * KP + p0 + seg * 4);
        }
        #pragma unroll
        for (int i = 0; i < 8; i++) {          // B: 128 rows x 8 segs
            const int s = tid + 128 * i;
            const int row = s >> 3, seg = s & 7;
            const uint32_t dst = bbase +
                (uint32_t)((seg >> 2) * BLKU + row * 16 + (seg & 3) * 4) * 4;
            cpasync16(dst, Bp + (size_t)(n0 + row) * KP + p0 + seg * 4);
        }
        asm volatile("cp.async.commit_group;" ::: "memory");
    };

    const int NCH = KP / 32;   // 20
    issue(0, 0);
    issue(1, 1);

    for (int c = 0; c < NCH; c++) {
        const int p = c % NSTAGE;
        if (c + 1 < NCH) {
            asm volatile("cp.async.wait_group 1;" ::: "memory");
        } else {
            asm volatile("cp.async.wait_group 0;" ::: "memory");
        }
        __syncthreads();

        if (c + 2 < NCH) issue(c + 2, (c + 2) % NSTAGE);

        const uint32_t* As = smu + p * SSTG2;
        const uint32_t* Bs = As + 2 * BLKU;

        #pragma unroll
        for (int kbk = 0; kbk < 2; kbk++) {
            const uint32_t* Ab = As + kbk * BLKU;
            const uint32_t* Bb = Bs + kbk * BLKU;
            uint4 a[4][2], b[8];
            #pragma unroll
            for (int im = 0; im < 4; im++) {
                const int row = wm * 64 + im * 16 + g;
                a[im][0] = *reinterpret_cast<const uint4*>(Ab + row * 16 + t * 4);
                a[im][1] = *reinterpret_cast<const uint4*>(Ab + (row + 8) * 16 + t * 4);
            }
            #pragma unroll
            for (int in = 0; in < 8; in++) {
                const int n = wn * 64 + in * 8 + g;
                b[in] = *reinterpret_cast<const uint4*>(Bb + n * 16 + t * 4);
            }
            #pragma unroll
            for (int ks = 0; ks < 2; ks++) {
                #pragma unroll
                for (int im = 0; im < 4; im++) {
                    const uint32_t a0 = ks ? a[im][0].z : a[im][0].x;
                    const uint32_t a2 = ks ? a[im][0].w : a[im][0].y;
                    const uint32_t a1 = ks ? a[im][1].z : a[im][1].x;
                    const uint32_t a3 = ks ? a[im][1].w : a[im][1].y;
                    #pragma unroll
                    for (int in = 0; in < 8; in++) {
                        const uint32_t b0 = ks ? b[in].z : b[in].x;
                        const uint32_t b1 = ks ? b[in].w : b[in].y;
                        mma_f16(cf[im][in], a0, a1, a2, a3, b0, b1);
                    }
                }
            }
        }
    }
    __syncthreads();

    // ---- epilogue: +bias; q/k fp32, v fp16 [b,h,d,s], out fp32 ----
    #pragma unroll
    for (int im = 0; im < 4; im++) {
        #pragma unroll
        for (int in = 0; in < 8; in++) {
            const int mrow0 = m0 + wm * 64 + im * 16 + g;
            const int ncol  = n0 + wn * 64 + in * 8 + 2 * t;
            const float2 bb = *reinterpret_cast<const float2*>(bias + ncol);
            #pragma unroll
            for (int h2 = 0; h2 < 2; h2++) {
                const int m = mrow0 + h2 * 8;
                float2 v;
                v.x = cf[im][in][h2 * 2 + 0] + bb.x;
                v.y = cf[im][in][h2 * 2 + 1] + bb.y;
                if (MODE == 0) {
                    const int b = m >> 10;
                    const int s = m & 1023;
                    const int which = ncol / CD;        // 0=q 1=k 2=v
                    const int r = ncol - which * CD;
                    const int h = r / CHD;
                    const int d = r - h * CHD;
                    if (which == 0) {
                        *reinterpret_cast<float2*>(
                            g_q + ((size_t)(b * CH + h) * CS + s) * CHD + d) = v;
                    } else if (which == 1) {
                        *reinterpret_cast<float2*>(
                            g_k + ((size_t)(b * CH + h) * CS + s) * CHD + d) = v;
                    } else {
                        const size_t vbase = ((size_t)(b * CH + h) * CHD + d) * CS + s;
                        g_vt[vbase]      = __float2half_rn(v.x);
                        g_vt[vbase + CS] = __float2half_rn(v.y);
                    }
                } else {
                    *reinterpret_cast<float2*>(out + (size_t)m * CD + ncol) = v;
                }
            }
        }
    }
}

// ============================================================================
// RoPE: fp32 q/k -> roped fp16x2 g_qp (pre-scaled), g_kp.
// ============================================================================
__global__ void __launch_bounds__(256)
rope_kernel(const float* __restrict__ cosb, const float* __restrict__ sinb)
{
    const int idx = blockIdx.x * blockDim.x + threadIdx.x;
    constexpr int TOT = CB * CH * CS * 20;
    if (idx >= TOT) return;
    const int j  = idx % 20;
    const int s  = (idx / 20) % CS;
    const int bh = idx / (20 * CS);

    const float2 c2 = *reinterpret_cast<const float2*>(cosb + s * CHD + 2 * j);
    const float2 s2 = *reinterpret_cast<const float2*>(sinb + s * CHD + 2 * j);
    const size_t base  = ((size_t)bh * CS + s) * CHD;
    const size_t pbase = ((size_t)bh * CS + s) * (CHD / 2);

    const float2 q1 = *reinterpret_cast<const float2*>(g_q + base + 2 * j);
    const float2 q2 = *reinterpret_cast<const float2*>(g_q + base + 40 + 2 * j);
    g_qp[pbase + j]      = f2h2((q1.x * c2.x - q2.x * s2.x) * ATTN_SCALE,
                                (q1.y * c2.y - q2.y * s2.y) * ATTN_SCALE);
    g_qp[pbase + 20 + j] = f2h2((q2.x * c2.x + q1.x * s2.x) * ATTN_SCALE,
                                (q2.y * c2.y + q1.y * s2.y) * ATTN_SCALE);

    const float2 k1 = *reinterpret_cast<const float2*>(g_k + base + 2 * j);
    const float2 k2 = *reinterpret_cast<const float2*>(g_k + base + 40 + 2 * j);
    g_kp[pbase + j]      = f2h2(k1.x * c2.x - k2.x * s2.x,
                                k1.y * c2.y - k2.y * s2.y);
    g_kp[pbase + 20 + j] = f2h2(k2.x * c2.x + k1.x * s2.x,
                                k2.y * c2.y + k1.y * s2.y);
}

// ============================================================================
// Fused flash attention, fp16 mma.sync, K/V double-buffered with prefetch.
// grid (S/64, B*H), 256 thr. Scores fp32, probs fp16.
// ============================================================================
__global__ void __launch_bounds__(256, 2)
attn_h()
{
    extern __shared__ uint32_t smu[];
    uint32_t* Qs = smu + OQ;                  // [64][PQH]
    uint32_t* Ks[2] = { smu + OK0, smu + OK1 };
    uint32_t* Vt[2] = { smu + OV0, smu + OV1 };
    float*    Psf = (float*)(smu + OSF);
    uint32_t* Ph  = smu + OPH;
    float*    sAlpha = (float*)(smu + OAL);
    float*    sL     = (float*)(smu + OL);
    const uint32_t smb = smem_u32(smu);
    const uint32_t qb = smb + OQ * 4;
    const uint32_t kbb[2] = { smb + OK0 * 4, smb + OK1 * 4 };
    const uint32_t vbb[2] = { smb + OV0 * 4, smb + OV1 * 4 };

    const int tid  = threadIdx.x;
    const int wid  = tid >> 5;
    const int lane = tid & 31;
    const int g    = lane >> 2;
    const int t    = lane & 3;
    const int wm   = wid & 1;
    const int wn   = wid >> 1;
    const int wq   = wid & 3;
    const int wd   = wid >> 2;
    const int srow = tid >> 2;
    const int sseg = tid & 3;

    const int bh = blockIdx.y;
    const int q0 = blockIdx.x * 64;

    const uint32_t* __restrict__ Qg = g_qp + (size_t)bh * CS * (CHD / 2);
    const uint32_t* __restrict__ Kg = g_kp + (size_t)bh * CS * (CHD / 2);
    const __half*   __restrict__ Vg = g_vt + (size_t)bh * CHD * CS;

    auto fill_kv = [&](int tt, int p) {
        #pragma unroll
        for (int i = 0; i < 3; i++) {
            const int c = tid + 256 * i;
            if (c < 640) {
                const int row = c / 10, seg = c % 10;
                cpasync16(kbb[p] + (uint32_t)(row * PKH + seg * 4) * 4,
                          Kg + (size_t)(tt + row) * 40 + seg * 4);
                const int d = c >> 3, sg = c & 7;
                cpasync16(vbb[p] + (uint32_t)(d * PVH + sg * 4) * 4,
                          Vg + (size_t)d * CS + tt + sg * 8);
            }
        }
        asm volatile("cp.async.commit_group;" ::: "memory");
    };

    // Q fill + first K/V tile
    #pragma unroll
    for (int i = 0; i < 3; i++) {
        const int c = tid + 256 * i;
        if (c < 640) {
            const int row = c / 10, seg = c % 10;
            cpasync16(qb + (uint32_t)(row * PQH + seg * 4) * 4,
                      Qg + (size_t)(q0 + row) * 40 + seg * 4);
        }
    }
    asm volatile("cp.async.commit_group;" ::: "memory");
    fill_kv(0, 0);

    float m_ = -1e30f, l_ = 0.f;
    float of[5][4];
    #pragma unroll
    for (int i = 0; i < 5; i++)
        #pragma unroll
        for (int r = 0; r < 4; r++) of[i][r] = 0.f;

    int p = 0;
    for (int tt = 0; tt < CS; tt += 64, p ^= 1) {
        asm volatile("cp.async.wait_group 0;" ::: "memory");
        __syncthreads();   // K/V buf p ready; prev iter's reads of buf p^1 done

        if (tt + 64 < CS) fill_kv(tt + 64, p ^ 1);

        const uint32_t* Kb = Ks[p];
        const uint32_t* Vb = Vt[p];

        // ---- S = Q K^T (64x64), warp tile 32x16, 5 k16 steps ----
        float sacc[2][2][4];
        #pragma unroll
        for (int im = 0; im < 2; im++)
            #pragma unroll
            for (int in = 0; in < 2; in++)
                #pragma unroll
                for (int r = 0; r < 4; r++) sacc[im][in][r] = 0.f;

        #pragma unroll
        for (int ks = 0; ks < 5; ks++) {
            uint32_t af[2][4], bf[2][2];
            #pragma unroll
            for (int im = 0; im < 2; im++) {
                const int row = wm * 32 + im * 16 + g;
                const int pc  = ks * 8 + t;
                af[im][0] = Qs[row * PQH + pc];
                af[im][1] = Qs[(row + 8) * PQH + pc];
                af[im][2] = Qs[row * PQH + pc + 4];
                af[im][3] = Qs[(row + 8) * PQH + pc + 4];
            }
            #pragma unroll
            for (int in = 0; in < 2; in++) {
                const int n = wn * 16 + in * 8 + g;
                bf[in][0] = Kb[n * PKH + ks * 8 + t];
                bf[in][1] = Kb[n * PKH + ks * 8 + t + 4];
            }
            #pragma unroll
            for (int im = 0; im < 2; im++)
                #pragma unroll
                for (int in = 0; in < 2; in++)
                    mma_f16(sacc[im][in], af[im][0], af[im][1], af[im][2], af[im][3],
                            bf[in][0], bf[in][1]);
        }
        #pragma unroll
        for (int im = 0; im < 2; im++) {
            const int r0 = wm * 32 + im * 16;
            #pragma unroll
            for (int in = 0; in < 2; in++) {
                const int cl = wn * 16 + in * 8 + 2 * t;
                *reinterpret_cast<float2*>(&Psf[(r0 + g) * PPF + cl]) =
                    make_float2(sacc[im][in][0], sacc[im][in][1]);
                *reinterpret_cast<float2*>(&Psf[(r0 + g + 8) * PPF + cl]) =
                    make_float2(sacc[im][in][2], sacc[im][in][3]);
            }
        }
        __syncthreads();

        // ---- online softmax: fp32 scores -> fp16 probs ----
        {
            const float* prow = Psf + srow * PPF + sseg * 16;
            float vals[16];
            float mx = -1e30f;
            #pragma unroll
            for (int j = 0; j < 16; j++) { vals[j] = prow[j]; mx = fmaxf(mx, vals[j]); }
            mx = fmaxf(mx, __shfl_xor_sync(0xffffffffu, mx, 1));
            mx = fmaxf(mx, __shfl_xor_sync(0xffffffffu, mx, 2));
            const float mnew  = fmaxf(m_, mx);
            const float alpha = __expf(m_ - mnew);
            float rs = 0.f;
            float pj[16];
            #pragma unroll
            for (int j = 0; j < 16; j++) {
                pj[j] = __expf(vals[j] - mnew);
                rs += pj[j];
            }
            uint32_t* ph = Ph + srow * PPH + sseg * 8;
            #pragma unroll
            for (int j = 0; j < 8; j++)
                ph[j] = f2h2(pj[2 * j], pj[2 * j + 1]);
            rs += __shfl_xor_sync(0xffffffffu, rs, 1);
            rs += __shfl_xor_sync(0xffffffffu, rs, 2);
            l_ = l_ * alpha + rs;
            m_ = mnew;
            if (sseg == 0) sAlpha[srow] = alpha;
        }
        __syncthreads();

        // ---- O = O*alpha + P @ V, warp tile 16x40, 4 k16 steps ----
        {
            const float aL = sAlpha[wq * 16 + g];
            const float aH = sAlpha[wq * 16 + g + 8];
            #pragma unroll
            for (int in = 0; in < 5; in++) {
                of[in][0] *= aL; of[in][1] *= aL;
                of[in][2] *= aH; of[in][3] *= aH;
            }
            #pragma unroll
            for (int ks = 0; ks < 4; ks++) {
                const int row = wq * 16 + g;
                const int pc  = ks * 8 + t;
                const uint32_t a0 = Ph[row * PPH + pc];
                const uint32_t a1 = Ph[(row + 8) * PPH + pc];
                const uint32_t a2 = Ph[row * PPH + pc + 4];
                const uint32_t a3 = Ph[(row + 8) * PPH + pc + 4];
                #pragma unroll
                for (int in = 0; in < 5; in++) {
                    const int n = wd * 40 + in * 8 + g;
                    const uint32_t b0 = Vb[n * PVH + pc];
                    const uint32_t b1 = Vb[n * PVH + pc + 4];
                    mma_f16(of[in], a0, a1, a2, a3, b0, b1);
                }
            }
        }
    }

    // ---- epilogue: write g_ctxp (fp16x2, pair-permuted) ----
    __syncthreads();
    if (sseg == 0) sL[srow] = l_;
    __syncthreads();

    const int b = bh >> 4, h = bh & 15;
    const float invL = 1.f / sL[wq * 16 + g];
    const float invH = 1.f / sL[wq * 16 + g + 8];
    const int rL = q0 + wq * 16 + g;
    const int rH = rL + 8;
    uint32_t* ctxL = g_ctxp + ((size_t)b * CS + rL) * KP;
    uint32_t* ctxH = g_ctxp + ((size_t)b * CS + rH) * KP;
    #pragma unroll
    for (int in = 0; in < 5; in++) {
        const int pairidx = h * 40 + wd * 20 + in * 4 + t;
        const int ppos = pperm(pairidx);
        ctxL[ppos] = f2h2(of[in][0] * invL, of[in][1] * invL);
        ctxH[ppos] = f2h2(of[in][2] * invH, of[in][3] * invH);
    }
}

// ============================================================================
// launch
// ============================================================================
extern "C" void kernel_launch(void* const* d_in, const int* in_sizes, int n_in,
                              void* d_out, int out_size)
{
    const float* x        = (const float*)d_in[0];
    const float* rope_cos = (const float*)d_in[1];
    const float* rope_sin = (const float*)d_in[2];
    const float* Wqkv     = (const float*)d_in[3];
    const float* bqkv     = (const float*)d_in[4];
    const float* Wproj    = (const float*)d_in[5];
    const float* bproj    = (const float*)d_in[6];
    float* out            = (float*)d_out;

    // 0) pre-convert / permute operands to fp16x2
    permA0<<<CM * KP / 256, 256>>>(x);
    transB<0><<<dim3(CNQKV / 32, CD / 32), dim3(32, 8)>>>(Wqkv);
    transB<1><<<dim3(CD / 32, CD / 32), dim3(32, 8)>>>(Wproj);

    // 1) QKV projection -> g_q/g_k (fp32), g_vt (fp16 [b,h,d,s])
    cudaFuncSetAttribute(gemm_h2<0>, cudaFuncAttributeMaxDynamicSharedMemorySize, GEMM_SMEM);
    gemm_h2<0><<<dim3(CNQKV / 128, CM / 128), 128, GEMM_SMEM>>>(bqkv, nullptr, CNQKV);

    // 2) RoPE -> g_qp (fp16, scaled), g_kp (fp16)
    {
        const int tot = CB * CH * CS * 20;
        rope_kernel<<<(tot + 255) / 256, 256>>>(rope_cos, rope_sin);
    }

    // 3) fused flash attention -> g_ctxp (fp16, permuted)
    cudaFuncSetAttribute(attn_h, cudaFuncAttributeMaxDynamicSharedMemorySize, ATTN_SMEM);
    attn_h<<<dim3(CS / 64, CB * CH), 256, ATTN_SMEM>>>();

    // 4) output projection -> d_out
    cudaFuncSetAttribute(gemm_h2<1>, cudaFuncAttributeMaxDynamicSharedMemorySize, GEMM_SMEM);
    gemm_h2<1><<<dim3(CD / 128, CM / 128), 128, GEMM_SMEM>>>(bproj, out, CD);
}

// round 14
// speedup vs baseline: 1.9775x; 1.0983x over previous
#include <cuda_runtime.h>
#include <cuda_fp16.h>
#include <cstdint>

// ---------------- problem constants ----------------
namespace {
constexpr int CB  = 4;      // batch
constexpr int CS  = 1024;   // seq
constexpr int CD  = 1280;   // model dim
constexpr int CH  = 16;     // heads
constexpr int CHD = 80;     // head dim
constexpr int CM  = CB * CS;          // 4096 rows
constexpr int CNQKV = 3 * CD;         // 3840
constexpr int KP  = CD / 2;           // 640 fp16 pairs per row

// dense GEMM (CTA 128x128, 4 warps 2x2, warp tile 64x64), fp16, 3-stage,
// chunk = 32 pairs stored as two 128x16 pitch-16 blocks (conflict-free).
constexpr int BLKU  = 128 * 16;                // u32 per block = 2048
constexpr int SSTG2 = 4 * BLKU;                // A(2 blk) + B(2 blk) = 8192 u32
constexpr int NSTAGE = 3;
constexpr int GEMM_SMEM = NSTAGE * SSTG2 * 4;  // 98,304 B (x2 CTAs = 192KB)

// attention smem (u32 units): Q[128] + double-buffered K[64]/V[80]
constexpr int PQH = 44;   // Qs pitch: frag bank 12g+t bijective
constexpr int PKH = 44;   // Ks pitch
constexpr int PVH = 36;   // Vt pitch: bank 4g+t bijective
constexpr int OQ   = 0;
constexpr int OK0  = OQ + 128 * PQH;       // 5632
constexpr int OK1  = OK0 + 64 * PKH;       // 8448
constexpr int OV0  = OK1 + 64 * PKH;       // 11264
constexpr int OV1  = OV0 + 80 * PVH;       // 14144
constexpr int ATTN_U32 = OV1 + 80 * PVH;   // 17024
constexpr int ATTN_SMEM = ATTN_U32 * 4;    // 68,096 B (x2 CTAs = 136KB)
}
#define ATTN_SCALE 0.11180339887498948f  // 80^-0.5

// ---------------- scratch (device globals; no allocs allowed) ----------------
__device__ __align__(16) float    g_q[CB * CH * CS * CHD];      // fp32 (pre-rope)
__device__ __align__(16) float    g_k[CB * CH * CS * CHD];      // fp32 (pre-rope)
__device__ __align__(16) uint32_t g_qp[CB * CH * CS * (CHD/2)]; // fp16x2, roped, *SCALE
__device__ __align__(16) uint32_t g_kp[CB * CH * CS * (CHD/2)]; // fp16x2, roped
__device__ __align__(16) __half   g_vt[CB * CH * CHD * CS];     // fp16, [b,h,d,s]
// fp16x2 pair-permuted GEMM operands
__device__ __align__(16) uint32_t g_xp[CM * KP];               // [m][p']
__device__ __align__(16) uint32_t g_ctxp[CM * KP];             // [m][p'] (from attn)
__device__ __align__(16) uint32_t g_wqkvp[CNQKV * KP];         // [n][p'] (transposed)
__device__ __align__(16) uint32_t g_wprojp[CD * KP];           // [n][p']

// ---------------- helpers ----------------
__device__ __forceinline__ uint32_t f2h2(float lo, float hi) {
    __half2 h = __floats2half2_rn(lo, hi);
    return *reinterpret_cast<uint32_t*>(&h);
}
__device__ __forceinline__ void mma_f16(float c[4],
                                        uint32_t a0, uint32_t a1, uint32_t a2, uint32_t a3,
                                        uint32_t b0, uint32_t b1) {
    asm volatile(
        "mma.sync.aligned.m16n8k16.row.col.f32.f16.f16.f32 "
        "{%0,%1,%2,%3}, {%4,%5,%6,%7}, {%8,%9}, {%0,%1,%2,%3};"
        : "+f"(c[0]), "+f"(c[1]), "+f"(c[2]), "+f"(c[3])
        : "r"(a0), "r"(a1), "r"(a2), "r"(a3), "r"(b0), "r"(b1));
}
__device__ __forceinline__ uint32_t smem_u32(const void* p) {
    uint32_t a;
    asm("{ .reg .u64 t; cvta.to.shared.u64 t, %1; cvt.u32.u64 %0, t; }"
        : "=r"(a) : "l"(p));
    return a;
}
__device__ __forceinline__ void cpasync16(uint32_t dst, const void* src) {
    asm volatile("cp.async.cg.shared.global [%0], [%1], 16;" :: "r"(dst), "l"(src));
}
// 4x4 pair permutation within each 16-pair block (involution): w' = (w%4)*4 + w/4
__device__ __forceinline__ int pperm(int p) {
    const int b = p & ~15, w = p & 15;
    return b + (w & 3) * 4 + (w >> 2);
}

// ============================================================================
// Pre-convert kernels
// ============================================================================
__global__ void __launch_bounds__(256)
permA0(const float* __restrict__ in)
{
    const int i = blockIdx.x * 256 + threadIdx.x;   // u32 output index
    const int m  = i / KP;
    const int pp = i - m * KP;
    const int pair = pperm(pp);
    const float* s = in + (size_t)m * CD + 2 * pair;
    g_xp[i] = f2h2(s[0], s[1]);
}

template <int MODE>
__global__ void transB(const float* __restrict__ W)
{
    uint32_t* __restrict__ out = MODE ? g_wprojp : g_wqkvp;
    const int N = MODE ? CD : CNQKV;
    __shared__ float tile[32][33];
    const int tx = threadIdx.x, ty = threadIdx.y;
    const int tid = ty * 32 + tx;
    const int nb = blockIdx.x, kb = blockIdx.y;
    #pragma unroll
    for (int r = 0; r < 4; r++) {
        const int kl = ty + 8 * r;
        tile[kl][tx] = W[(size_t)(kb * 32 + kl) * N + nb * 32 + tx];
    }
    __syncthreads();
    #pragma unroll
    for (int i = 0; i < 2; i++) {
        const int o = tid + 256 * i;        // 512 outputs: 32 n x 16 pairs
        const int n  = o >> 4;
        const int w1 = o & 15;
        const int w  = (w1 & 3) * 4 + (w1 >> 2);
        out[(size_t)(nb * 32 + n) * KP + kb * 16 + w1] =
            f2h2(tile[2 * w][n], tile[2 * w + 1][n]);
    }
}

// ============================================================================
// fp16 mma.sync GEMM (R13 winner, unchanged): chunk = 32 pairs.
// ============================================================================
template <int MODE>
__global__ void __launch_bounds__(128)
gemm_h2(const float* __restrict__ bias, float* __restrict__ out, int N)
{
    const uint32_t* __restrict__ Ap = MODE ? g_ctxp : g_xp;
    const uint32_t* __restrict__ Bp = MODE ? g_wprojp : g_wqkvp;

    extern __shared__ uint32_t smu[];
    const uint32_t smbase = smem_u32(smu);

    const int tid  = threadIdx.x;
    const int wid  = tid >> 5;
    const int lane = tid & 31;
    const int g    = lane >> 2;
    const int t    = lane & 3;
    const int wm   = wid & 1;
    const int wn   = wid >> 1;
    const int m0   = blockIdx.y * 128;
    const int n0   = blockIdx.x * 128;

    float cf[4][8][4];
    #pragma unroll
    for (int im = 0; im < 4; im++)
        #pragma unroll
        for (int in = 0; in < 8; in++)
            #pragma unroll
            for (int r = 0; r < 4; r++) cf[im][in][r] = 0.f;

    auto issue = [&](int c, int p) {
        const uint32_t abase = smbase + (uint32_t)p * SSTG2 * 4;
        const uint32_t bbase = abase + 2 * BLKU * 4;
        const int p0 = c * 32;
        #pragma unroll
        for (int i = 0; i < 8; i++) {          // A: 128 rows x 8 segs
            const int s = tid + 128 * i;
            const int row = s >> 3, seg = s & 7;
            const uint32_t dst = abase +
                (uint32_t)((seg >> 2) * BLKU + row * 16 + (seg & 3) * 4) * 4;
            cpasync16(dst, Ap + (size_t)(m0 + row) * KP + p0 + seg * 4);
        }
        #pragma unroll
        for (int i = 0; i < 8; i++) {          // B: 128 rows x 8 segs
            const int s = tid + 128 * i;
            const int row = s >> 3, seg = s & 7;
            const uint32_t dst = bbase +
                (uint32_t)((seg >> 2) * BLKU + row * 16 + (seg & 3) * 4) * 4;
            cpasync16(dst, Bp + (size_t)(n0 + row) * KP + p0 + seg * 4);
        }
        asm volatile("cp.async.commit_group;" ::: "memory");
    };

    const int NCH = KP / 32;   // 20
    issue(0, 0);
    issue(1, 1);

    for (int c = 0; c < NCH; c++) {
        const int p = c % NSTAGE;
        if (c + 1 < NCH) {
            asm volatile("cp.async.wait_group 1;" ::: "memory");
        } else {
            asm volatile("cp.async.wait_group 0;" ::: "memory");
        }
        __syncthreads();

        if (c + 2 < NCH) issue(c + 2, (c + 2) % NSTAGE);

        const uint32_t* As = smu + p * SSTG2;
        const uint32_t* Bs = As + 2 * BLKU;

        #pragma unroll
        for (int kbk = 0; kbk < 2; kbk++) {
            const uint32_t* Ab = As + kbk * BLKU;
            const uint32_t* Bb = Bs + kbk * BLKU;
            uint4 a[4][2], b[8];
            #pragma unroll
            for (int im = 0; im < 4; im++) {
                const int row = wm * 64 + im * 16 + g;
                a[im][0] = *reinterpret_cast<const uint4*>(Ab + row * 16 + t * 4);
                a[im][1] = *reinterpret_cast<const uint4*>(Ab + (row + 8) * 16 + t * 4);
            }
            #pragma unroll
            for (int in = 0; in < 8; in++) {
                const int n = wn * 64 + in * 8 + g;
                b[in] = *reinterpret_cast<const uint4*>(Bb + n * 16 + t * 4);
            }
            #pragma unroll
            for (int ks = 0; ks < 2; ks++) {
                #pragma unroll
                for (int im = 0; im < 4; im++) {
                    const uint32_t a0 = ks ? a[im][0].z : a[im][0].x;
                    const uint32_t a2 = ks ? a[im][0].w : a[im][0].y;
                    const uint32_t a1 = ks ? a[im][1].z : a[im][1].x;
                    const uint32_t a3 = ks ? a[im][1].w : a[im][1].y;
                    #pragma unroll
                    for (int in = 0; in < 8; in++) {
                        const uint32_t b0 = ks ? b[in].z : b[in].x;
                        const uint32_t b1 = ks ? b[in].w : b[in].y;
                        mma_f16(cf[im][in], a0, a1, a2, a3, b0, b1);
                    }
                }
            }
        }
    }
    __syncthreads();

    // ---- epilogue: +bias; q/k fp32, v fp16 [b,h,d,s], out fp32 ----
    #pragma unroll
    for (int im = 0; im < 4; im++) {
        #pragma unroll
        for (int in = 0; in < 8; in++) {
            const int mrow0 = m0 + wm * 64 + im * 16 + g;
            const int ncol  = n0 + wn * 64 + in * 8 + 2 * t;
            const float2 bb = *reinterpret_cast<const float2*>(bias + ncol);
            #pragma unroll
            for (int h2 = 0; h2 < 2; h2++) {
                const int m = mrow0 + h2 * 8;
                float2 v;
                v.x = cf[im][in][h2 * 2 + 0] + bb.x;
                v.y = cf[im][in][h2 * 2 + 1] + bb.y;
                if (MODE == 0) {
                    const int b = m >> 10;
                    const int s = m & 1023;
                    const int which = ncol / CD;        // 0=q 1=k 2=v
                    const int r = ncol - which * CD;
                    const int h = r / CHD;
                    const int d = r - h * CHD;
                    if (which == 0) {
                        *reinterpret_cast<float2*>(
                            g_q + ((size_t)(b * CH + h) * CS + s) * CHD + d) = v;
                    } else if (which == 1) {
                        *reinterpret_cast<float2*>(
                            g_k + ((size_t)(b * CH + h) * CS + s) * CHD + d) = v;
                    } else {
                        const size_t vbase = ((size_t)(b * CH + h) * CHD + d) * CS + s;
                        g_vt[vbase]      = __float2half_rn(v.x);
                        g_vt[vbase + CS] = __float2half_rn(v.y);
                    }
                } else {
                    *reinterpret_cast<float2*>(out + (size_t)m * CD + ncol) = v;
                }
            }
        }
    }
}

// ============================================================================
// RoPE: fp32 q/k -> roped fp16x2 g_qp (pre-scaled), g_kp.
// ============================================================================
__global__ void __launch_bounds__(256)
rope_kernel(const float* __restrict__ cosb, const float* __restrict__ sinb)
{
    const int idx = blockIdx.x * blockDim.x + threadIdx.x;
    constexpr int TOT = CB * CH * CS * 20;
    if (idx >= TOT) return;
    const int j  = idx % 20;
    const int s  = (idx / 20) % CS;
    const int bh = idx / (20 * CS);

    const float2 c2 = *reinterpret_cast<const float2*>(cosb + s * CHD + 2 * j);
    const float2 s2 = *reinterpret_cast<const float2*>(sinb + s * CHD + 2 * j);
    const size_t base  = ((size_t)bh * CS + s) * CHD;
    const size_t pbase = ((size_t)bh * CS + s) * (CHD / 2);

    const float2 q1 = *reinterpret_cast<const float2*>(g_q + base + 2 * j);
    const float2 q2 = *reinterpret_cast<const float2*>(g_q + base + 40 + 2 * j);
    g_qp[pbase + j]      = f2h2((q1.x * c2.x - q2.x * s2.x) * ATTN_SCALE,
                                (q1.y * c2.y - q2.y * s2.y) * ATTN_SCALE);
    g_qp[pbase + 20 + j] = f2h2((q2.x * c2.x + q1.x * s2.x) * ATTN_SCALE,
                                (q2.y * c2.y + q1.y * s2.y) * ATTN_SCALE);

    const float2 k1 = *reinterpret_cast<const float2*>(g_k + base + 2 * j);
    const float2 k2 = *reinterpret_cast<const float2*>(g_k + base + 40 + 2 * j);
    g_kp[pbase + j]      = f2h2(k1.x * c2.x - k2.x * s2.x,
                                k1.y * c2.y - k2.y * s2.y);
    g_kp[pbase + 20 + j] = f2h2(k2.x * c2.x + k1.x * s2.x,
                                k2.y * c2.y + k1.y * s2.y);
}

// ============================================================================
// Fused flash attention v2 (FA2-style): BQ=128, 8 warps, each warp owns 16
// q-rows x full 64 kv-cols. Softmax entirely in registers (quad shfl);
// P fragments feed PV directly (C-frag == A-frag identity). K/V double-
// buffered cp.async; ONE barrier per tile. No softmax smem at all.
// ============================================================================
__global__ void __launch_bounds__(256, 2)
attn_h2()
{
    extern __shared__ uint32_t smu[];
    uint32_t* Qs = smu + OQ;                        // [128][PQH]
    uint32_t* Ks[2] = { smu + OK0, smu + OK1 };     // [64][PKH]
    uint32_t* Vt[2] = { smu + OV0, smu + OV1 };     // [80][PVH]
    const uint32_t smb = smem_u32(smu);
    const uint32_t qb = smb + OQ * 4;
    const uint32_t kbb[2] = { smb + OK0 * 4, smb + OK1 * 4 };
    const uint32_t vbb[2] = { smb + OV0 * 4, smb + OV1 * 4 };

    const int tid  = threadIdx.x;
    const int wid  = tid >> 5;       // warp owns q-rows [16*wid, 16*wid+16)
    const int lane = tid & 31;
    const int g    = lane >> 2;
    const int t    = lane & 3;

    const int bh = blockIdx.y;
    const int q0 = blockIdx.x * 128;

    const uint32_t* __restrict__ Qg = g_qp + (size_t)bh * CS * (CHD / 2);
    const uint32_t* __restrict__ Kg = g_kp + (size_t)bh * CS * (CHD / 2);
    const __half*   __restrict__ Vg = g_vt + (size_t)bh * CHD * CS;

    auto fill_kv = [&](int tt, int p) {
        #pragma unroll
        for (int i = 0; i < 3; i++) {
            const int c = tid + 256 * i;
            if (c < 640) {
                const int row = c / 10, seg = c % 10;
                cpasync16(kbb[p] + (uint32_t)(row * PKH + seg * 4) * 4,
                          Kg + (size_t)(tt + row) * 40 + seg * 4);
                const int d = c >> 3, sg = c & 7;
                cpasync16(vbb[p] + (uint32_t)(d * PVH + sg * 4) * 4,
                          Vg + (size_t)d * CS + tt + sg * 8);
            }
        }
        asm volatile("cp.async.commit_group;" ::: "memory");
    };

    // Q fill: 128 rows x 10 segs = 1280 chunks, exactly 5 per thread
    #pragma unroll
    for (int i = 0; i < 5; i++) {
        const int c = tid + 256 * i;
        const int row = c / 10, seg = c % 10;
        cpasync16(qb + (uint32_t)(row * PQH + seg * 4) * 4,
                  Qg + (size_t)(q0 + row) * 40 + seg * 4);
    }
    asm volatile("cp.async.commit_group;" ::: "memory");
    fill_kv(0, 0);

    float mL = -1e30f, mH = -1e30f, lL = 0.f, lH = 0.f;
    float of[10][4];
    #pragma unroll
    for (int i = 0; i < 10; i++)
        #pragma unroll
        for (int r = 0; r < 4; r++) of[i][r] = 0.f;

    int p = 0;
    for (int tt = 0; tt < CS; tt += 64, p ^= 1) {
        asm volatile("cp.async.wait_group 0;" ::: "memory");
        __syncthreads();   // buf p ready; all prev reads of buf p^1 done

        if (tt + 64 < CS) fill_kv(tt + 64, p ^ 1);

        const uint32_t* Kb = Ks[p];
        const uint32_t* Vb = Vt[p];

        // ---- S = Q K^T : warp tile 16 x 64 (8 n8 tiles), 5 k16 steps ----
        float sacc[8][4];
        #pragma unroll
        for (int in = 0; in < 8; in++)
            #pragma unroll
            for (int r = 0; r < 4; r++) sacc[in][r] = 0.f;

        #pragma unroll
        for (int ks = 0; ks < 5; ks++) {
            const int row = wid * 16 + g;
            const int pc  = ks * 8 + t;
            const uint32_t a0 = Qs[row * PQH + pc];
            const uint32_t a1 = Qs[(row + 8) * PQH + pc];
            const uint32_t a2 = Qs[row * PQH + pc + 4];
            const uint32_t a3 = Qs[(row + 8) * PQH + pc + 4];
            #pragma unroll
            for (int in = 0; in < 8; in++) {
                const int n = in * 8 + g;
                const uint32_t b0 = Kb[n * PKH + ks * 8 + t];
                const uint32_t b1 = Kb[n * PKH + ks * 8 + t + 4];
                mma_f16(sacc[in], a0, a1, a2, a3, b0, b1);
            }
        }

        // ---- register-resident online softmax (rows g and g+8) ----
        float mxL = -1e30f, mxH = -1e30f;
        #pragma unroll
        for (int in = 0; in < 8; in++) {
            mxL = fmaxf(mxL, fmaxf(sacc[in][0], sacc[in][1]));
            mxH = fmaxf(mxH, fmaxf(sacc[in][2], sacc[in][3]));
        }
        mxL = fmaxf(mxL, __shfl_xor_sync(0xffffffffu, mxL, 1));
        mxL = fmaxf(mxL, __shfl_xor_sync(0xffffffffu, mxL, 2));
        mxH = fmaxf(mxH, __shfl_xor_sync(0xffffffffu, mxH, 1));
        mxH = fmaxf(mxH, __shfl_xor_sync(0xffffffffu, mxH, 2));
        const float mnL = fmaxf(mL, mxL);
        const float mnH = fmaxf(mH, mxH);
        const float aL = __expf(mL - mnL);
        const float aH = __expf(mH - mnH);
        float rsL = 0.f, rsH = 0.f;
        #pragma unroll
        for (int in = 0; in < 8; in++) {
            sacc[in][0] = __expf(sacc[in][0] - mnL);
            sacc[in][1] = __expf(sacc[in][1] - mnL);
            sacc[in][2] = __expf(sacc[in][2] - mnH);
            sacc[in][3] = __expf(sacc[in][3] - mnH);
            rsL += sacc[in][0] + sacc[in][1];
            rsH += sacc[in][2] + sacc[in][3];
        }
        rsL += __shfl_xor_sync(0xffffffffu, rsL, 1);
        rsL += __shfl_xor_sync(0xffffffffu, rsL, 2);
        rsH += __shfl_xor_sync(0xffffffffu, rsH, 1);
        rsH += __shfl_xor_sync(0xffffffffu, rsH, 2);
        lL = lL * aL + rsL;  mL = mnL;
        lH = lH * aH + rsH;  mH = mnH;

        // ---- pack P into A-fragments (C-frag == A-frag identity) ----
        uint32_t pa[4][4];
        #pragma unroll
        for (int ks = 0; ks < 4; ks++) {
            pa[ks][0] = f2h2(sacc[2 * ks][0],     sacc[2 * ks][1]);
            pa[ks][1] = f2h2(sacc[2 * ks][2],     sacc[2 * ks][3]);
            pa[ks][2] = f2h2(sacc[2 * ks + 1][0], sacc[2 * ks + 1][1]);
            pa[ks][3] = f2h2(sacc[2 * ks + 1][2], sacc[2 * ks + 1][3]);
        }

        // ---- O = O*alpha + P @ V : warp tile 16 x 80 (10 n8), 4 k16 ----
        #pragma unroll
        for (int in = 0; in < 10; in++) {
            of[in][0] *= aL; of[in][1] *= aL;
            of[in][2] *= aH; of[in][3] *= aH;
        }
        #pragma unroll
        for (int ks = 0; ks < 4; ks++) {
            #pragma unroll
            for (int in = 0; in < 10; in++) {
                const int n = in * 8 + g;
                const uint32_t b0 = Vb[n * PVH + ks * 8 + t];
                const uint32_t b1 = Vb[n * PVH + ks * 8 + t + 4];
                mma_f16(of[in], pa[ks][0], pa[ks][1], pa[ks][2], pa[ks][3], b0, b1);
            }
        }
    }

    // ---- epilogue: normalize (own rows!), write g_ctxp fp16x2 permuted ----
    const int b = bh >> 4, h = bh & 15;
    const float invL = 1.f / lL;
    const float invH = 1.f / lH;
    const int rL = q0 + wid * 16 + g;
    const int rH = rL + 8;
    uint32_t* ctxL = g_ctxp + ((size_t)b * CS + rL) * KP;
    uint32_t* ctxH = g_ctxp + ((size_t)b * CS + rH) * KP;
    #pragma unroll
    for (int in = 0; in < 10; in++) {
        const int pairidx = h * 40 + in * 4 + t;   // col (8*in + 2t)/2 within head
        const int ppos = pperm(pairidx);
        ctxL[ppos] = f2h2(of[in][0] * invL, of[in][1] * invL);
        ctxH[ppos] = f2h2(of[in][2] * invH, of[in][3] * invH);
    }
}

// ============================================================================
// launch
// ============================================================================
extern "C" void kernel_launch(void* const* d_in, const int* in_sizes, int n_in,
                              void* d_out, int out_size)
{
    const float* x        = (const float*)d_in[0];
    const float* rope_cos = (const float*)d_in[1];
    const float* rope_sin = (const float*)d_in[2];
    const float* Wqkv     = (const float*)d_in[3];
    const float* bqkv     = (const float*)d_in[4];
    const float* Wproj    = (const float*)d_in[5];
    const float* bproj    = (const float*)d_in[6];
    float* out            = (float*)d_out;

    // 0) pre-convert / permute operands to fp16x2
    permA0<<<CM * KP / 256, 256>>>(x);
    transB<0><<<dim3(CNQKV / 32, CD / 32), dim3(32, 8)>>>(Wqkv);
    transB<1><<<dim3(CD / 32, CD / 32), dim3(32, 8)>>>(Wproj);

    // 1) QKV projection -> g_q/g_k (fp32), g_vt (fp16 [b,h,d,s])
    cudaFuncSetAttribute(gemm_h2<0>, cudaFuncAttributeMaxDynamicSharedMemorySize, GEMM_SMEM);
    gemm_h2<0><<<dim3(CNQKV / 128, CM / 128), 128, GEMM_SMEM>>>(bqkv, nullptr, CNQKV);

    // 2) RoPE -> g_qp (fp16, scaled), g_kp (fp16)
    {
        const int tot = CB * CH * CS * 20;
        rope_kernel<<<(tot + 255) / 256, 256>>>(rope_cos, rope_sin);
    }

    // 3) fused flash attention (FA2 register softmax) -> g_ctxp
    cudaFuncSetAttribute(attn_h2, cudaFuncAttributeMaxDynamicSharedMemorySize, ATTN_SMEM);
    attn_h2<<<dim3(CS / 128, CB * CH), 256, ATTN_SMEM>>>();

    // 4) output projection -> d_out
    cudaFuncSetAttribute(gemm_h2<1>, cudaFuncAttributeMaxDynamicSharedMemorySize, GEMM_SMEM);
    gemm_h2<1><<<dim3(CD / 128, CM / 128), 128, GEMM_SMEM>>>(bproj, out, CD);
}

// round 15
// speedup vs baseline: 1.9977x; 1.0102x over previous
#include <cuda_runtime.h>
#include <cuda_fp16.h>
#include <cstdint>

// ---------------- problem constants ----------------
namespace {
constexpr int CB  = 4;      // batch
constexpr int CS  = 1024;   // seq
constexpr int CD  = 1280;   // model dim
constexpr int CH  = 16;     // heads
constexpr int CHD = 80;     // head dim
constexpr int CM  = CB * CS;          // 4096 rows
constexpr int CNQKV = 3 * CD;         // 3840
constexpr int KP  = CD / 2;           // 640 fp16 pairs per row

// dense GEMM (CTA 128x128, 4 warps 2x2, warp tile 64x64), fp16, 3-stage,
// chunk = 32 pairs stored as two 128x16 pitch-16 blocks (conflict-free).
constexpr int BLKU  = 128 * 16;                // u32 per block = 2048
constexpr int SSTG2 = 4 * BLKU;                // A(2 blk) + B(2 blk) = 8192 u32
constexpr int NSTAGE = 3;
constexpr int GEMM_SMEM = NSTAGE * SSTG2 * 4;  // 98,304 B (x2 CTAs = 192KB)

// attention smem (u32 units): Q[128] + double-buffered K[64]/V[80]
constexpr int PQH = 44;   // Qs pitch: frag bank 12g+t bijective
constexpr int PKH = 44;   // Ks pitch
constexpr int PVH = 36;   // Vt pitch: bank 4g+t bijective
constexpr int OQ   = 0;
constexpr int OK0  = OQ + 128 * PQH;       // 5632
constexpr int OK1  = OK0 + 64 * PKH;       // 8448
constexpr int OV0  = OK1 + 64 * PKH;       // 11264
constexpr int OV1  = OV0 + 80 * PVH;       // 14144
constexpr int ATTN_U32 = OV1 + 80 * PVH;   // 17024
constexpr int ATTN_SMEM = ATTN_U32 * 4;    // 68,096 B (x2 CTAs = 136KB)

// merged prep kernel block ranges
constexpr int PREP_A_BLKS  = CM * KP / 256;            // 10240
constexpr int PREP_B0_NB   = CNQKV / 32;               // 120
constexpr int PREP_B0_BLKS = PREP_B0_NB * (CD / 32);   // 4800
constexpr int PREP_B1_NB   = CD / 32;                  // 40
constexpr int PREP_B1_BLKS = PREP_B1_NB * (CD / 32);   // 1600
constexpr int PREP_TOTAL   = PREP_A_BLKS + PREP_B0_BLKS + PREP_B1_BLKS;
}
#define ATTN_SCALE 0.11180339887498948f  // 80^-0.5

// ---------------- scratch (device globals; no allocs allowed) ----------------
__device__ __align__(16) float    g_q[CB * CH * CS * CHD];      // fp32 (pre-rope)
__device__ __align__(16) float    g_k[CB * CH * CS * CHD];      // fp32 (pre-rope)
__device__ __align__(16) uint32_t g_qp[CB * CH * CS * (CHD/2)]; // fp16x2, roped, *SCALE
__device__ __align__(16) uint32_t g_kp[CB * CH * CS * (CHD/2)]; // fp16x2, roped
__device__ __align__(16) __half   g_vt[CB * CH * CHD * CS];     // fp16, [b,h,d,s]
// fp16x2 pair-permuted GEMM operands
__device__ __align__(16) uint32_t g_xp[CM * KP];               // [m][p']
__device__ __align__(16) uint32_t g_ctxp[CM * KP];             // [m][p'] (from attn)
__device__ __align__(16) uint32_t g_wqkvp[CNQKV * KP];         // [n][p'] (transposed)
__device__ __align__(16) uint32_t g_wprojp[CD * KP];           // [n][p']

// ---------------- helpers ----------------
__device__ __forceinline__ uint32_t f2h2(float lo, float hi) {
    __half2 h = __floats2half2_rn(lo, hi);
    return *reinterpret_cast<uint32_t*>(&h);
}
__device__ __forceinline__ void mma_f16(float c[4],
                                        uint32_t a0, uint32_t a1, uint32_t a2, uint32_t a3,
                                        uint32_t b0, uint32_t b1) {
    asm volatile(
        "mma.sync.aligned.m16n8k16.row.col.f32.f16.f16.f32 "
        "{%0,%1,%2,%3}, {%4,%5,%6,%7}, {%8,%9}, {%0,%1,%2,%3};"
        : "+f"(c[0]), "+f"(c[1]), "+f"(c[2]), "+f"(c[3])
        : "r"(a0), "r"(a1), "r"(a2), "r"(a3), "r"(b0), "r"(b1));
}
__device__ __forceinline__ uint32_t smem_u32(const void* p) {
    uint32_t a;
    asm("{ .reg .u64 t; cvta.to.shared.u64 t, %1; cvt.u32.u64 %0, t; }"
        : "=r"(a) : "l"(p));
    return a;
}
__device__ __forceinline__ void cpasync16(uint32_t dst, const void* src) {
    asm volatile("cp.async.cg.shared.global [%0], [%1], 16;" :: "r"(dst), "l"(src));
}
// 4x4 pair permutation within each 16-pair block (involution): w' = (w%4)*4 + w/4
__device__ __forceinline__ int pperm(int p) {
    const int b = p & ~15, w = p & 15;
    return b + (w & 3) * 4 + (w >> 2);
}

// ============================================================================
// Merged prep kernel: one launch does permA0 + transB(Wqkv) + transB(Wproj).
// Block ranges: [0,PREP_A_BLKS) = x convert; next = Wqkv; next = Wproj.
// ============================================================================
__global__ void __launch_bounds__(256)
prep_all(const float* __restrict__ x,
         const float* __restrict__ Wqkv,
         const float* __restrict__ Wproj)
{
    const int blk = blockIdx.x;
    const int tid = threadIdx.x;

    if (blk < PREP_A_BLKS) {
        // ---- x [M][K] fp32 -> g_xp [m][p'] fp16x2 pair-permuted ----
        const int i = blk * 256 + tid;
        const int m  = i / KP;
        const int pp = i - m * KP;
        const int pair = pperm(pp);
        const float* s = x + (size_t)m * CD + 2 * pair;
        g_xp[i] = f2h2(s[0], s[1]);
        return;
    }

    // ---- weight transpose + convert ----
    const bool is0 = (blk < PREP_A_BLKS + PREP_B0_BLKS);
    const int  rb  = blk - (is0 ? PREP_A_BLKS : PREP_A_BLKS + PREP_B0_BLKS);
    const float* __restrict__ W = is0 ? Wqkv : Wproj;
    uint32_t* __restrict__ out  = is0 ? g_wqkvp : g_wprojp;
    const int N  = is0 ? CNQKV : CD;
    const int NB = is0 ? PREP_B0_NB : PREP_B1_NB;
    const int nb = rb % NB;
    const int kb = rb / NB;

    __shared__ float tile[32][33];
    const int tx = tid & 31, ty = tid >> 5;
    #pragma unroll
    for (int r = 0; r < 4; r++) {
        const int kl = ty + 8 * r;
        tile[kl][tx] = W[(size_t)(kb * 32 + kl) * N + nb * 32 + tx];
    }
    __syncthreads();
    #pragma unroll
    for (int i = 0; i < 2; i++) {
        const int o = tid + 256 * i;        // 512 outputs: 32 n x 16 pairs
        const int n  = o >> 4;
        const int w1 = o & 15;
        const int w  = (w1 & 3) * 4 + (w1 >> 2);
        out[(size_t)(nb * 32 + n) * KP + kb * 16 + w1] =
            f2h2(tile[2 * w][n], tile[2 * w + 1][n]);
    }
}

// ============================================================================
// fp16 mma.sync GEMM: chunk = 32 pairs (two 128x16 pitch-16 blocks).
// 128 threads (4 warps 2x2), warp tile 64x64. 20 chunks, 3-stage cp.async.
// Reordered: kbk=0 fragment LDS before issuing next chunk's cp.async.
// MODE 0: scatter q/k fp32 + v fp16 [b,h,d,s].  MODE 1: -> out fp32.
// ============================================================================
template <int MODE>
__global__ void __launch_bounds__(128)
gemm_h2(const float* __restrict__ bias, float* __restrict__ out, int N)
{
    const uint32_t* __restrict__ Ap = MODE ? g_ctxp : g_xp;
    const uint32_t* __restrict__ Bp = MODE ? g_wprojp : g_wqkvp;

    extern __shared__ uint32_t smu[];
    const uint32_t smbase = smem_u32(smu);

    const int tid  = threadIdx.x;
    const int wid  = tid >> 5;
    const int lane = tid & 31;
    const int g    = lane >> 2;
    const int t    = lane & 3;
    const int wm   = wid & 1;
    const int wn   = wid >> 1;
    const int m0   = blockIdx.y * 128;
    const int n0   = blockIdx.x * 128;

    float cf[4][8][4];
    #pragma unroll
    for (int im = 0; im < 4; im++)
        #pragma unroll
        for (int in = 0; in < 8; in++)
            #pragma unroll
            for (int r = 0; r < 4; r++) cf[im][in][r] = 0.f;

    auto issue = [&](int c, int p) {
        const uint32_t abase = smbase + (uint32_t)p * SSTG2 * 4;
        const uint32_t bbase = abase + 2 * BLKU * 4;
        const int p0 = c * 32;
        #pragma unroll
        for (int i = 0; i < 8; i++) {          // A: 128 rows x 8 segs
            const int s = tid + 128 * i;
            const int row = s >> 3, seg = s & 7;
            const uint32_t dst = abase +
                (uint32_t)((seg >> 2) * BLKU + row * 16 + (seg & 3) * 4) * 4;
            cpasync16(dst, Ap + (size_t)(m0 + row) * KP + p0 + seg * 4);
        }
        #pragma unroll
        for (int i = 0; i < 8; i++) {          // B: 128 rows x 8 segs
            const int s = tid + 128 * i;
            const int row = s >> 3, seg = s & 7;
            const uint32_t dst = bbase +
                (uint32_t)((seg >> 2) * BLKU + row * 16 + (seg & 3) * 4) * 4;
            cpasync16(dst, Bp + (size_t)(n0 + row) * KP + p0 + seg * 4);
        }
        asm volatile("cp.async.commit_group;" ::: "memory");
    };

    const int NCH = KP / 32;   // 20
    issue(0, 0);
    issue(1, 1);

    for (int c = 0; c < NCH; c++) {
        const int p = c % NSTAGE;
        if (c + 1 < NCH) {
            asm volatile("cp.async.wait_group 1;" ::: "memory");
        } else {
            asm volatile("cp.async.wait_group 0;" ::: "memory");
        }
        __syncthreads();

        const uint32_t* As = smu + p * SSTG2;
        const uint32_t* Bs = As + 2 * BLKU;

        // ---- kbk=0 fragment loads FIRST (so they aren't queued behind
        //      the 16 cp.async issues below) ----
        uint4 a0f[4][2], b0f[8];
        #pragma unroll
        for (int im = 0; im < 4; im++) {
            const int row = wm * 64 + im * 16 + g;
            a0f[im][0] = *reinterpret_cast<const uint4*>(As + row * 16 + t * 4);
            a0f[im][1] = *reinterpret_cast<const uint4*>(As + (row + 8) * 16 + t * 4);
        }
        #pragma unroll
        for (int in = 0; in < 8; in++) {
            const int n = wn * 64 + in * 8 + g;
            b0f[in] = *reinterpret_cast<const uint4*>(Bs + n * 16 + t * 4);
        }

        if (c + 2 < NCH) issue(c + 2, (c + 2) % NSTAGE);

        // ---- compute kbk=0 ----
        #pragma unroll
        for (int ks = 0; ks < 2; ks++) {
            #pragma unroll
            for (int im = 0; im < 4; im++) {
                const uint32_t a0 = ks ? a0f[im][0].z : a0f[im][0].x;
                const uint32_t a2 = ks ? a0f[im][0].w : a0f[im][0].y;
                const uint32_t a1 = ks ? a0f[im][1].z : a0f[im][1].x;
                const uint32_t a3 = ks ? a0f[im][1].w : a0f[im][1].y;
                #pragma unroll
                for (int in = 0; in < 8; in++) {
                    const uint32_t b0 = ks ? b0f[in].z : b0f[in].x;
                    const uint32_t b1 = ks ? b0f[in].w : b0f[in].y;
                    mma_f16(cf[im][in], a0, a1, a2, a3, b0, b1);
                }
            }
        }

        // ---- kbk=1 load + compute ----
        {
            const uint32_t* Ab = As + BLKU;
            const uint32_t* Bb = Bs + BLKU;
            uint4 a[4][2], b[8];
            #pragma unroll
            for (int im = 0; im < 4; im++) {
                const int row = wm * 64 + im * 16 + g;
                a[im][0] = *reinterpret_cast<const uint4*>(Ab + row * 16 + t * 4);
                a[im][1] = *reinterpret_cast<const uint4*>(Ab + (row + 8) * 16 + t * 4);
            }
            #pragma unroll
            for (int in = 0; in < 8; in++) {
                const int n = wn * 64 + in * 8 + g;
                b[in] = *reinterpret_cast<const uint4*>(Bb + n * 16 + t * 4);
            }
            #pragma unroll
            for (int ks = 0; ks < 2; ks++) {
                #pragma unroll
                for (int im = 0; im < 4; im++) {
                    const uint32_t a0 = ks ? a[im][0].z : a[im][0].x;
                    const uint32_t a2 = ks ? a[im][0].w : a[im][0].y;
                    const uint32_t a1 = ks ? a[im][1].z : a[im][1].x;
                    const uint32_t a3 = ks ? a[im][1].w : a[im][1].y;
                    #pragma unroll
                    for (int in = 0; in < 8; in++) {
                        const uint32_t b0 = ks ? b[in].z : b[in].x;
                        const uint32_t b1 = ks ? b[in].w : b[in].y;
                        mma_f16(cf[im][in], a0, a1, a2, a3, b0, b1);
                    }
                }
            }
        }
    }
    __syncthreads();

    // ---- epilogue: +bias; q/k fp32, v fp16 [b,h,d,s], out fp32 ----
    #pragma unroll
    for (int im = 0; im < 4; im++) {
        #pragma unroll
        for (int in = 0; in < 8; in++) {
            const int mrow0 = m0 + wm * 64 + im * 16 + g;
            const int ncol  = n0 + wn * 64 + in * 8 + 2 * t;
            const float2 bb = *reinterpret_cast<const float2*>(bias + ncol);
            #pragma unroll
            for (int h2 = 0; h2 < 2; h2++) {
                const int m = mrow0 + h2 * 8;
                float2 v;
                v.x = cf[im][in][h2 * 2 + 0] + bb.x;
                v.y = cf[im][in][h2 * 2 + 1] + bb.y;
                if (MODE == 0) {
                    const int b = m >> 10;
                    const int s = m & 1023;
                    const int which = ncol / CD;        // 0=q 1=k 2=v
                    const int r = ncol - which * CD;
                    const int h = r / CHD;
                    const int d = r - h * CHD;
                    if (which == 0) {
                        *reinterpret_cast<float2*>(
                            g_q + ((size_t)(b * CH + h) * CS + s) * CHD + d) = v;
                    } else if (which == 1) {
                        *reinterpret_cast<float2*>(
                            g_k + ((size_t)(b * CH + h) * CS + s) * CHD + d) = v;
                    } else {
                        const size_t vbase = ((size_t)(b * CH + h) * CHD + d) * CS + s;
                        g_vt[vbase]      = __float2half_rn(v.x);
                        g_vt[vbase + CS] = __float2half_rn(v.y);
                    }
                } else {
                    *reinterpret_cast<float2*>(out + (size_t)m * CD + ncol) = v;
                }
            }
        }
    }
}

// ============================================================================
// RoPE: fp32 q/k -> roped fp16x2 g_qp (pre-scaled), g_kp.
// ============================================================================
__global__ void __launch_bounds__(256)
rope_kernel(const float* __restrict__ cosb, const float* __restrict__ sinb)
{
    const int idx = blockIdx.x * blockDim.x + threadIdx.x;
    constexpr int TOT = CB * CH * CS * 20;
    if (idx >= TOT) return;
    const int j  = idx % 20;
    const int s  = (idx / 20) % CS;
    const int bh = idx / (20 * CS);

    const float2 c2 = *reinterpret_cast<const float2*>(cosb + s * CHD + 2 * j);
    const float2 s2 = *reinterpret_cast<const float2*>(sinb + s * CHD + 2 * j);
    const size_t base  = ((size_t)bh * CS + s) * CHD;
    const size_t pbase = ((size_t)bh * CS + s) * (CHD / 2);

    const float2 q1 = *reinterpret_cast<const float2*>(g_q + base + 2 * j);
    const float2 q2 = *reinterpret_cast<const float2*>(g_q + base + 40 + 2 * j);
    g_qp[pbase + j]      = f2h2((q1.x * c2.x - q2.x * s2.x) * ATTN_SCALE,
                                (q1.y * c2.y - q2.y * s2.y) * ATTN_SCALE);
    g_qp[pbase + 20 + j] = f2h2((q2.x * c2.x + q1.x * s2.x) * ATTN_SCALE,
                                (q2.y * c2.y + q1.y * s2.y) * ATTN_SCALE);

    const float2 k1 = *reinterpret_cast<const float2*>(g_k + base + 2 * j);
    const float2 k2 = *reinterpret_cast<const float2*>(g_k + base + 40 + 2 * j);
    g_kp[pbase + j]      = f2h2(k1.x * c2.x - k2.x * s2.x,
                                k1.y * c2.y - k2.y * s2.y);
    g_kp[pbase + 20 + j] = f2h2(k2.x * c2.x + k1.x * s2.x,
                                k2.y * c2.y + k1.y * s2.y);
}

// ============================================================================
// Fused flash attention v2 (FA2 register softmax) — R14 winner, unchanged.
// ============================================================================
__global__ void __launch_bounds__(256, 2)
attn_h2()
{
    extern __shared__ uint32_t smu[];
    uint32_t* Qs = smu + OQ;                        // [128][PQH]
    uint32_t* Ks[2] = { smu + OK0, smu + OK1 };     // [64][PKH]
    uint32_t* Vt[2] = { smu + OV0, smu + OV1 };     // [80][PVH]
    const uint32_t smb = smem_u32(smu);
    const uint32_t qb = smb + OQ * 4;
    const uint32_t kbb[2] = { smb + OK0 * 4, smb + OK1 * 4 };
    const uint32_t vbb[2] = { smb + OV0 * 4, smb + OV1 * 4 };

    const int tid  = threadIdx.x;
    const int wid  = tid >> 5;       // warp owns q-rows [16*wid, 16*wid+16)
    const int lane = tid & 31;
    const int g    = lane >> 2;
    const int t    = lane & 3;

    const int bh = blockIdx.y;
    const int q0 = blockIdx.x * 128;

    const uint32_t* __restrict__ Qg = g_qp + (size_t)bh * CS * (CHD / 2);
    const uint32_t* __restrict__ Kg = g_kp + (size_t)bh * CS * (CHD / 2);
    const __half*   __restrict__ Vg = g_vt + (size_t)bh * CHD * CS;

    auto fill_kv = [&](int tt, int p) {
        #pragma unroll
        for (int i = 0; i < 3; i++) {
            const int c = tid + 256 * i;
            if (c < 640) {
                const int row = c / 10, seg = c % 10;
                cpasync16(kbb[p] + (uint32_t)(row * PKH + seg * 4) * 4,
                          Kg + (size_t)(tt + row) * 40 + seg * 4);
                const int d = c >> 3, sg = c & 7;
                cpasync16(vbb[p] + (uint32_t)(d * PVH + sg * 4) * 4,
                          Vg + (size_t)d * CS + tt + sg * 8);
            }
        }
        asm volatile("cp.async.commit_group;" ::: "memory");
    };

    // Q fill: 128 rows x 10 segs = 1280 chunks, exactly 5 per thread
    #pragma unroll
    for (int i = 0; i < 5; i++) {
        const int c = tid + 256 * i;
        const int row = c / 10, seg = c % 10;
        cpasync16(qb + (uint32_t)(row * PQH + seg * 4) * 4,
                  Qg + (size_t)(q0 + row) * 40 + seg * 4);
    }
    asm volatile("cp.async.commit_group;" ::: "memory");
    fill_kv(0, 0);

    float mL = -1e30f, mH = -1e30f, lL = 0.f, lH = 0.f;
    float of[10][4];
    #pragma unroll
    for (int i = 0; i < 10; i++)
        #pragma unroll
        for (int r = 0; r < 4; r++) of[i][r] = 0.f;

    int p = 0;
    for (int tt = 0; tt < CS; tt += 64, p ^= 1) {
        asm volatile("cp.async.wait_group 0;" ::: "memory");
        __syncthreads();   // buf p ready; all prev reads of buf p^1 done

        if (tt + 64 < CS) fill_kv(tt + 64, p ^ 1);

        const uint32_t* Kb = Ks[p];
        const uint32_t* Vb = Vt[p];

        // ---- S = Q K^T : warp tile 16 x 64 (8 n8 tiles), 5 k16 steps ----
        float sacc[8][4];
        #pragma unroll
        for (int in = 0; in < 8; in++)
            #pragma unroll
            for (int r = 0; r < 4; r++) sacc[in][r] = 0.f;

        #pragma unroll
        for (int ks = 0; ks < 5; ks++) {
            const int row = wid * 16 + g;
            const int pc  = ks * 8 + t;
            const uint32_t a0 = Qs[row * PQH + pc];
            const uint32_t a1 = Qs[(row + 8) * PQH + pc];
            const uint32_t a2 = Qs[row * PQH + pc + 4];
            const uint32_t a3 = Qs[(row + 8) * PQH + pc + 4];
            #pragma unroll
            for (int in = 0; in < 8; in++) {
                const int n = in * 8 + g;
                const uint32_t b0 = Kb[n * PKH + ks * 8 + t];
                const uint32_t b1 = Kb[n * PKH + ks * 8 + t + 4];
                mma_f16(sacc[in], a0, a1, a2, a3, b0, b1);
            }
        }

        // ---- register-resident online softmax (rows g and g+8) ----
        float mxL = -1e30f, mxH = -1e30f;
        #pragma unroll
        for (int in = 0; in < 8; in++) {
            mxL = fmaxf(mxL, fmaxf(sacc[in][0], sacc[in][1]));
            mxH = fmaxf(mxH, fmaxf(sacc[in][2], sacc[in][3]));
        }
        mxL = fmaxf(mxL, __shfl_xor_sync(0xffffffffu, mxL, 1));
        mxL = fmaxf(mxL, __shfl_xor_sync(0xffffffffu, mxL, 2));
        mxH = fmaxf(mxH, __shfl_xor_sync(0xffffffffu, mxH, 1));
        mxH = fmaxf(mxH, __shfl_xor_sync(0xffffffffu, mxH, 2));
        const float mnL = fmaxf(mL, mxL);
        const float mnH = fmaxf(mH, mxH);
        const float aL = __expf(mL - mnL);
        const float aH = __expf(mH - mnH);
        float rsL = 0.f, rsH = 0.f;
        #pragma unroll
        for (int in = 0; in < 8; in++) {
            sacc[in][0] = __expf(sacc[in][0] - mnL);
            sacc[in][1] = __expf(sacc[in][1] - mnL);
            sacc[in][2] = __expf(sacc[in][2] - mnH);
            sacc[in][3] = __expf(sacc[in][3] - mnH);
            rsL += sacc[in][0] + sacc[in][1];
            rsH += sacc[in][2] + sacc[in][3];
        }
        rsL += __shfl_xor_sync(0xffffffffu, rsL, 1);
        rsL += __shfl_xor_sync(0xffffffffu, rsL, 2);
        rsH += __shfl_xor_sync(0xffffffffu, rsH, 1);
        rsH += __shfl_xor_sync(0xffffffffu, rsH, 2);
        lL = lL * aL + rsL;  mL = mnL;
        lH = lH * aH + rsH;  mH = mnH;

        // ---- pack P into A-fragments (C-frag == A-frag identity) ----
        uint32_t pa[4][4];
        #pragma unroll
        for (int ks = 0; ks < 4; ks++) {
            pa[ks][0] = f2h2(sacc[2 * ks][0],     sacc[2 * ks][1]);
            pa[ks][1] = f2h2(sacc[2 * ks][2],     sacc[2 * ks][3]);
            pa[ks][2] = f2h2(sacc[2 * ks + 1][0], sacc[2 * ks + 1][1]);
            pa[ks][3] = f2h2(sacc[2 * ks + 1][2], sacc[2 * ks + 1][3]);
        }

        // ---- O = O*alpha + P @ V : warp tile 16 x 80 (10 n8), 4 k16 ----
        #pragma unroll
        for (int in = 0; in < 10; in++) {
            of[in][0] *= aL; of[in][1] *= aL;
            of[in][2] *= aH; of[in][3] *= aH;
        }
        #pragma unroll
        for (int ks = 0; ks < 4; ks++) {
            #pragma unroll
            for (int in = 0; in < 10; in++) {
                const int n = in * 8 + g;
                const uint32_t b0 = Vb[n * PVH + ks * 8 + t];
                const uint32_t b1 = Vb[n * PVH + ks * 8 + t + 4];
                mma_f16(of[in], pa[ks][0], pa[ks][1], pa[ks][2], pa[ks][3], b0, b1);
            }
        }
    }

    // ---- epilogue: normalize (own rows), write g_ctxp fp16x2 permuted ----
    const int b = bh >> 4, h = bh & 15;
    const float invL = 1.f / lL;
    const float invH = 1.f / lH;
    const int rL = q0 + wid * 16 + g;
    const int rH = rL + 8;
    uint32_t* ctxL = g_ctxp + ((size_t)b * CS + rL) * KP;
    uint32_t* ctxH = g_ctxp + ((size_t)b * CS + rH) * KP;
    #pragma unroll
    for (int in = 0; in < 10; in++) {
        const int pairidx = h * 40 + in * 4 + t;
        const int ppos = pperm(pairidx);
        ctxL[ppos] = f2h2(of[in][0] * invL, of[in][1] * invL);
        ctxH[ppos] = f2h2(of[in][2] * invH, of[in][3] * invH);
    }
}

// ============================================================================
// launch
// ============================================================================
extern "C" void kernel_launch(void* const* d_in, const int* in_sizes, int n_in,
                              void* d_out, int out_size)
{
    const float* x        = (const float*)d_in[0];
    const float* rope_cos = (const float*)d_in[1];
    const float* rope_sin = (const float*)d_in[2];
    const float* Wqkv     = (const float*)d_in[3];
    const float* bqkv     = (const float*)d_in[4];
    const float* Wproj    = (const float*)d_in[5];
    const float* bproj    = (const float*)d_in[6];
    float* out            = (float*)d_out;

    // 0) merged prep: x + both weights -> fp16x2 permuted operands
    prep_all<<<PREP_TOTAL, 256>>>(x, Wqkv, Wproj);

    // 1) QKV projection -> g_q/g_k (fp32), g_vt (fp16 [b,h,d,s])
    cudaFuncSetAttribute(gemm_h2<0>, cudaFuncAttributeMaxDynamicSharedMemorySize, GEMM_SMEM);
    gemm_h2<0><<<dim3(CNQKV / 128, CM / 128), 128, GEMM_SMEM>>>(bqkv, nullptr, CNQKV);

    // 2) RoPE -> g_qp (fp16, scaled), g_kp (fp16)
    {
        const int tot = CB * CH * CS * 20;
        rope_kernel<<<(tot + 255) / 256, 256>>>(rope_cos, rope_sin);
    }

    // 3) fused flash attention (FA2 register softmax) -> g_ctxp
    cudaFuncSetAttribute(attn_h2, cudaFuncAttributeMaxDynamicSharedMemorySize, ATTN_SMEM);
    attn_h2<<<dim3(CS / 128, CB * CH), 256, ATTN_SMEM>>>();

    // 4) output projection -> d_out
    cudaFuncSetAttribute(gemm_h2<1>, cudaFuncAttributeMaxDynamicSharedMemorySize, GEMM_SMEM);
    gemm_h2<1><<<dim3(CD / 128, CM / 128), 128, GEMM_SMEM>>>(bproj, out, CD);
}

// round 16
// speedup vs baseline: 2.1461x; 1.0743x over previous
#include <cuda_runtime.h>
#include <cuda_fp16.h>
#include <cstdint>

// ---------------- problem constants ----------------
namespace {
constexpr int CB  = 4;      // batch
constexpr int CS  = 1024;   // seq
constexpr int CD  = 1280;   // model dim
constexpr int CH  = 16;     // heads
constexpr int CHD = 80;     // head dim
constexpr int CM  = CB * CS;          // 4096 rows
constexpr int CNQKV = 3 * CD;         // 3840
constexpr int KP  = CD / 2;           // 640 fp16 pairs per row

// dense GEMM (CTA 128x128, 4 warps 2x2, warp tile 64x64), fp16, 3-stage,
// chunk = 32 pairs stored as two 128x16 pitch-16 blocks (conflict-free).
constexpr int BLKU  = 128 * 16;                // u32 per block = 2048
constexpr int SSTG2 = 4 * BLKU;                // A(2 blk) + B(2 blk) = 8192 u32
constexpr int NSTAGE = 3;
constexpr int GEMM_SMEM = NSTAGE * SSTG2 * 4;  // 98,304 B (x2 CTAs = 192KB)

// attention smem (u32 units): Q[128] + double-buffered K[64]/V[80].
// All pitches 40 (== 8 mod 32 -> conflict-free LDS.64 half-warp phases).
constexpr int PQH = 40;
constexpr int PKH = 40;
constexpr int PVH = 40;
constexpr int OQ   = 0;
constexpr int OK0  = OQ + 128 * PQH;       // 5120
constexpr int OK1  = OK0 + 64 * PKH;       // 7680
constexpr int OV0  = OK1 + 64 * PKH;       // 10240
constexpr int OV1  = OV0 + 80 * PVH;       // 13440
constexpr int ATTN_U32 = OV1 + 80 * PVH;   // 16640
constexpr int ATTN_SMEM = ATTN_U32 * 4;    // 66,560 B (x2 CTAs = 133KB)

// merged prep kernel block ranges
constexpr int PREP_A_BLKS  = CM * KP / 256;            // 10240
constexpr int PREP_B0_NB   = CNQKV / 32;               // 120
constexpr int PREP_B0_BLKS = PREP_B0_NB * (CD / 32);   // 4800
constexpr int PREP_B1_NB   = CD / 32;                  // 40
constexpr int PREP_B1_BLKS = PREP_B1_NB * (CD / 32);   // 1600
constexpr int PREP_TOTAL   = PREP_A_BLKS + PREP_B0_BLKS + PREP_B1_BLKS;
}
#define ATTN_SCALE 0.11180339887498948f  // 80^-0.5
#define LOG2E      1.4426950408889634f

// ---------------- scratch (device globals; no allocs allowed) ----------------
__device__ __align__(16) float    g_q[CB * CH * CS * CHD];      // fp32 (pre-rope)
__device__ __align__(16) float    g_k[CB * CH * CS * CHD];      // fp32 (pre-rope)
__device__ __align__(16) uint32_t g_qp[CB * CH * CS * (CHD/2)]; // fp16x2, roped, *SCALE*log2e, 8-interleaved
__device__ __align__(16) uint32_t g_kp[CB * CH * CS * (CHD/2)]; // fp16x2, roped, 8-interleaved
__device__ __align__(16) __half   g_vt[CB * CH * CHD * CS];     // fp16, [b,h,d,s] s-pairs 8-interleaved
// fp16x2 pair-permuted GEMM operands
__device__ __align__(16) uint32_t g_xp[CM * KP];               // [m][p']
__device__ __align__(16) uint32_t g_ctxp[CM * KP];             // [m][p'] (from attn)
__device__ __align__(16) uint32_t g_wqkvp[CNQKV * KP];         // [n][p'] (transposed)
__device__ __align__(16) uint32_t g_wprojp[CD * KP];           // [n][p']

// ---------------- helpers ----------------
__device__ __forceinline__ uint32_t f2h2(float lo, float hi) {
    __half2 h = __floats2half2_rn(lo, hi);
    return *reinterpret_cast<uint32_t*>(&h);
}
__device__ __forceinline__ void mma_f16(float c[4],
                                        uint32_t a0, uint32_t a1, uint32_t a2, uint32_t a3,
                                        uint32_t b0, uint32_t b1) {
    asm volatile(
        "mma.sync.aligned.m16n8k16.row.col.f32.f16.f16.f32 "
        "{%0,%1,%2,%3}, {%4,%5,%6,%7}, {%8,%9}, {%0,%1,%2,%3};"
        : "+f"(c[0]), "+f"(c[1]), "+f"(c[2]), "+f"(c[3])
        : "r"(a0), "r"(a1), "r"(a2), "r"(a3), "r"(b0), "r"(b1));
}
__device__ __forceinline__ uint32_t smem_u32(const void* p) {
    uint32_t a;
    asm("{ .reg .u64 t; cvta.to.shared.u64 t, %1; cvt.u32.u64 %0, t; }"
        : "=r"(a) : "l"(p));
    return a;
}
__device__ __forceinline__ void cpasync16(uint32_t dst, const void* src) {
    asm volatile("cp.async.cg.shared.global [%0], [%1], 16;" :: "r"(dst), "l"(src));
}
// 4x4 pair permutation within each 16-pair block (involution): w' = (w%4)*4 + w/4
__device__ __forceinline__ int pperm(int p) {
    const int b = p & ~15, w = p & 15;
    return b + (w & 3) * 4 + (w >> 2);
}
// 8-group interleave [0,4,1,5,2,6,3,7]: pair w -> position 2*(w&3) + (w>>2)
__device__ __forceinline__ int ip8(int p) {
    const int b = p & ~7, w = p & 7;
    return b + 2 * (w & 3) + (w >> 2);
}

// ============================================================================
// Merged prep kernel: one launch does permA0 + transB(Wqkv) + transB(Wproj).
// ============================================================================
__global__ void __launch_bounds__(256)
prep_all(const float* __restrict__ x,
         const float* __restrict__ Wqkv,
         const float* __restrict__ Wproj)
{
    const int blk = blockIdx.x;
    const int tid = threadIdx.x;

    if (blk < PREP_A_BLKS) {
        const int i = blk * 256 + tid;
        const int m  = i / KP;
        const int pp = i - m * KP;
        const int pair = pperm(pp);
        const float* s = x + (size_t)m * CD + 2 * pair;
        g_xp[i] = f2h2(s[0], s[1]);
        return;
    }

    const bool is0 = (blk < PREP_A_BLKS + PREP_B0_BLKS);
    const int  rb  = blk - (is0 ? PREP_A_BLKS : PREP_A_BLKS + PREP_B0_BLKS);
    const float* __restrict__ W = is0 ? Wqkv : Wproj;
    uint32_t* __restrict__ out  = is0 ? g_wqkvp : g_wprojp;
    const int N  = is0 ? CNQKV : CD;
    const int NB = is0 ? PREP_B0_NB : PREP_B1_NB;
    const int nb = rb % NB;
    const int kb = rb / NB;

    __shared__ float tile[32][33];
    const int tx = tid & 31, ty = tid >> 5;
    #pragma unroll
    for (int r = 0; r < 4; r++) {
        const int kl = ty + 8 * r;
        tile[kl][tx] = W[(size_t)(kb * 32 + kl) * N + nb * 32 + tx];
    }
    __syncthreads();
    #pragma unroll
    for (int i = 0; i < 2; i++) {
        const int o = tid + 256 * i;
        const int n  = o >> 4;
        const int w1 = o & 15;
        const int w  = (w1 & 3) * 4 + (w1 >> 2);
        out[(size_t)(nb * 32 + n) * KP + kb * 16 + w1] =
            f2h2(tile[2 * w][n], tile[2 * w + 1][n]);
    }
}

// ============================================================================
// fp16 mma.sync GEMM (R15 winner): chunk = 32 pairs.
// MODE 0: scatter q/k fp32 + v fp16 [b,h,d,s] (s-pairs 8-interleaved).
// MODE 1: -> out fp32.
// ============================================================================
template <int MODE>
__global__ void __launch_bounds__(128)
gemm_h2(const float* __restrict__ bias, float* __restrict__ out, int N)
{
    const uint32_t* __restrict__ Ap = MODE ? g_ctxp : g_xp;
    const uint32_t* __restrict__ Bp = MODE ? g_wprojp : g_wqkvp;

    extern __shared__ uint32_t smu[];
    const uint32_t smbase = smem_u32(smu);

    const int tid  = threadIdx.x;
    const int wid  = tid >> 5;
    const int lane = tid & 31;
    const int g    = lane >> 2;
    const int t    = lane & 3;
    const int wm   = wid & 1;
    const int wn   = wid >> 1;
    const int m0   = blockIdx.y * 128;
    const int n0   = blockIdx.x * 128;

    float cf[4][8][4];
    #pragma unroll
    for (int im = 0; im < 4; im++)
        #pragma unroll
        for (int in = 0; in < 8; in++)
            #pragma unroll
            for (int r = 0; r < 4; r++) cf[im][in][r] = 0.f;

    auto issue = [&](int c, int p) {
        const uint32_t abase = smbase + (uint32_t)p * SSTG2 * 4;
        const uint32_t bbase = abase + 2 * BLKU * 4;
        const int p0 = c * 32;
        #pragma unroll
        for (int i = 0; i < 8; i++) {
            const int s = tid + 128 * i;
            const int row = s >> 3, seg = s & 7;
            const uint32_t dst = abase +
                (uint32_t)((seg >> 2) * BLKU + row * 16 + (seg & 3) * 4) * 4;
            cpasync16(dst, Ap + (size_t)(m0 + row) * KP + p0 + seg * 4);
        }
        #pragma unroll
        for (int i = 0; i < 8; i++) {
            const int s = tid + 128 * i;
            const int row = s >> 3, seg = s & 7;
            const uint32_t dst = bbase +
                (uint32_t)((seg >> 2) * BLKU + row * 16 + (seg & 3) * 4) * 4;
            cpasync16(dst, Bp + (size_t)(n0 + row) * KP + p0 + seg * 4);
        }
        asm volatile("cp.async.commit_group;" ::: "memory");
    };

    const int NCH = KP / 32;   // 20
    issue(0, 0);
    issue(1, 1);

    for (int c = 0; c < NCH; c++) {
        const int p = c % NSTAGE;
        if (c + 1 < NCH) {
            asm volatile("cp.async.wait_group 1;" ::: "memory");
        } else {
            asm volatile("cp.async.wait_group 0;" ::: "memory");
        }
        __syncthreads();

        const uint32_t* As = smu + p * SSTG2;
        const uint32_t* Bs = As + 2 * BLKU;

        uint4 a0f[4][2], b0f[8];
        #pragma unroll
        for (int im = 0; im < 4; im++) {
            const int row = wm * 64 + im * 16 + g;
            a0f[im][0] = *reinterpret_cast<const uint4*>(As + row * 16 + t * 4);
            a0f[im][1] = *reinterpret_cast<const uint4*>(As + (row + 8) * 16 + t * 4);
        }
        #pragma unroll
        for (int in = 0; in < 8; in++) {
            const int n = wn * 64 + in * 8 + g;
            b0f[in] = *reinterpret_cast<const uint4*>(Bs + n * 16 + t * 4);
        }

        if (c + 2 < NCH) issue(c + 2, (c + 2) % NSTAGE);

        #pragma unroll
        for (int ks = 0; ks < 2; ks++) {
            #pragma unroll
            for (int im = 0; im < 4; im++) {
                const uint32_t a0 = ks ? a0f[im][0].z : a0f[im][0].x;
                const uint32_t a2 = ks ? a0f[im][0].w : a0f[im][0].y;
                const uint32_t a1 = ks ? a0f[im][1].z : a0f[im][1].x;
                const uint32_t a3 = ks ? a0f[im][1].w : a0f[im][1].y;
                #pragma unroll
                for (int in = 0; in < 8; in++) {
                    const uint32_t b0 = ks ? b0f[in].z : b0f[in].x;
                    const uint32_t b1 = ks ? b0f[in].w : b0f[in].y;
                    mma_f16(cf[im][in], a0, a1, a2, a3, b0, b1);
                }
            }
        }

        {
            const uint32_t* Ab = As + BLKU;
            const uint32_t* Bb = Bs + BLKU;
            uint4 a[4][2], b[8];
            #pragma unroll
            for (int im = 0; im < 4; im++) {
                const int row = wm * 64 + im * 16 + g;
                a[im][0] = *reinterpret_cast<const uint4*>(Ab + row * 16 + t * 4);
                a[im][1] = *reinterpret_cast<const uint4*>(Ab + (row + 8) * 16 + t * 4);
            }
            #pragma unroll
            for (int in = 0; in < 8; in++) {
                const int n = wn * 64 + in * 8 + g;
                b[in] = *reinterpret_cast<const uint4*>(Bb + n * 16 + t * 4);
            }
            #pragma unroll
            for (int ks = 0; ks < 2; ks++) {
                #pragma unroll
                for (int im = 0; im < 4; im++) {
                    const uint32_t a0 = ks ? a[im][0].z : a[im][0].x;
                    const uint32_t a2 = ks ? a[im][0].w : a[im][0].y;
                    const uint32_t a1 = ks ? a[im][1].z : a[im][1].x;
                    const uint32_t a3 = ks ? a[im][1].w : a[im][1].y;
                    #pragma unroll
                    for (int in = 0; in < 8; in++) {
                        const uint32_t b0 = ks ? b[in].z : b[in].x;
                        const uint32_t b1 = ks ? b[in].w : b[in].y;
                        mma_f16(cf[im][in], a0, a1, a2, a3, b0, b1);
                    }
                }
            }
        }
    }
    __syncthreads();

    // ---- epilogue ----
    #pragma unroll
    for (int im = 0; im < 4; im++) {
        #pragma unroll
        for (int in = 0; in < 8; in++) {
            const int mrow0 = m0 + wm * 64 + im * 16 + g;
            const int ncol  = n0 + wn * 64 + in * 8 + 2 * t;
            const float2 bb = *reinterpret_cast<const float2*>(bias + ncol);
            #pragma unroll
            for (int h2 = 0; h2 < 2; h2++) {
                const int m = mrow0 + h2 * 8;
                float2 v;
                v.x = cf[im][in][h2 * 2 + 0] + bb.x;
                v.y = cf[im][in][h2 * 2 + 1] + bb.y;
                if (MODE == 0) {
                    const int b = m >> 10;
                    const int s = m & 1023;
                    const int which = ncol / CD;        // 0=q 1=k 2=v
                    const int r = ncol - which * CD;
                    const int h = r / CHD;
                    const int d = r - h * CHD;
                    if (which == 0) {
                        *reinterpret_cast<float2*>(
                            g_q + ((size_t)(b * CH + h) * CS + s) * CHD + d) = v;
                    } else if (which == 1) {
                        *reinterpret_cast<float2*>(
                            g_k + ((size_t)(b * CH + h) * CS + s) * CHD + d) = v;
                    } else {
                        // s-pair 8-interleaved position
                        const int sp = 2 * ip8(s >> 1) + (s & 1);
                        const size_t vbase = ((size_t)(b * CH + h) * CHD + d) * CS + sp;
                        g_vt[vbase]      = __float2half_rn(v.x);
                        g_vt[vbase + CS] = __float2half_rn(v.y);
                    }
                } else {
                    *reinterpret_cast<float2*>(out + (size_t)m * CD + ncol) = v;
                }
            }
        }
    }
}

// ============================================================================
// RoPE: fp32 q/k -> roped fp16x2, 8-interleaved pair layout.
// q pre-scaled by SCALE*log2e (softmax runs in exp2 domain).
// ============================================================================
__global__ void __launch_bounds__(256)
rope_kernel(const float* __restrict__ cosb, const float* __restrict__ sinb)
{
    const int idx = blockIdx.x * blockDim.x + threadIdx.x;
    constexpr int TOT = CB * CH * CS * 20;
    if (idx >= TOT) return;
    const int j  = idx % 20;
    const int s  = (idx / 20) % CS;
    const int bh = idx / (20 * CS);

    const float QSC = ATTN_SCALE * LOG2E;

    const float2 c2 = *reinterpret_cast<const float2*>(cosb + s * CHD + 2 * j);
    const float2 s2 = *reinterpret_cast<const float2*>(sinb + s * CHD + 2 * j);
    const size_t base  = ((size_t)bh * CS + s) * CHD;
    const size_t pbase = ((size_t)bh * CS + s) * (CHD / 2);
    const int pj0 = ip8(j);
    const int pj1 = ip8(j + 20);

    const float2 q1 = *reinterpret_cast<const float2*>(g_q + base + 2 * j);
    const float2 q2 = *reinterpret_cast<const float2*>(g_q + base + 40 + 2 * j);
    g_qp[pbase + pj0] = f2h2((q1.x * c2.x - q2.x * s2.x) * QSC,
                             (q1.y * c2.y - q2.y * s2.y) * QSC);
    g_qp[pbase + pj1] = f2h2((q2.x * c2.x + q1.x * s2.x) * QSC,
                             (q2.y * c2.y + q1.y * s2.y) * QSC);

    const float2 k1 = *reinterpret_cast<const float2*>(g_k + base + 2 * j);
    const float2 k2 = *reinterpret_cast<const float2*>(g_k + base + 40 + 2 * j);
    g_kp[pbase + pj0] = f2h2(k1.x * c2.x - k2.x * s2.x,
                             k1.y * c2.y - k2.y * s2.y);
    g_kp[pbase + pj1] = f2h2(k2.x * c2.x + k1.x * s2.x,
                             k2.y * c2.y + k1.y * s2.y);
}

// ============================================================================
// Fused flash attention v3: FA2 register softmax + uint2 fragment loads
// (8-interleaved layouts) + exp2-domain softmax.
// ============================================================================
__global__ void __launch_bounds__(256, 2)
attn_h2()
{
    extern __shared__ uint32_t smu[];
    uint32_t* Qs = smu + OQ;                        // [128][40]
    uint32_t* Ks[2] = { smu + OK0, smu + OK1 };     // [64][40]
    uint32_t* Vt[2] = { smu + OV0, smu + OV1 };     // [80][40]
    const uint32_t smb = smem_u32(smu);
    const uint32_t qb = smb + OQ * 4;
    const uint32_t kbb[2] = { smb + OK0 * 4, smb + OK1 * 4 };
    const uint32_t vbb[2] = { smb + OV0 * 4, smb + OV1 * 4 };

    const int tid  = threadIdx.x;
    const int wid  = tid >> 5;
    const int lane = tid & 31;
    const int g    = lane >> 2;
    const int t    = lane & 3;

    const int bh = blockIdx.y;
    const int q0 = blockIdx.x * 128;

    const uint32_t* __restrict__ Qg = g_qp + (size_t)bh * CS * (CHD / 2);
    const uint32_t* __restrict__ Kg = g_kp + (size_t)bh * CS * (CHD / 2);
    const __half*   __restrict__ Vg = g_vt + (size_t)bh * CHD * CS;

    auto fill_kv = [&](int tt, int p) {
        #pragma unroll
        for (int i = 0; i < 3; i++) {
            const int c = tid + 256 * i;
            if (c < 640) {
                const int row = c / 10, seg = c % 10;
                cpasync16(kbb[p] + (uint32_t)(row * PKH + seg * 4) * 4,
                          Kg + (size_t)(tt + row) * 40 + seg * 4);
                const int d = c >> 3, sg = c & 7;
                cpasync16(vbb[p] + (uint32_t)(d * PVH + sg * 4) * 4,
                          Vg + (size_t)d * CS + tt + sg * 8);
            }
        }
        asm volatile("cp.async.commit_group;" ::: "memory");
    };

    // Q fill: 128 rows x 10 segs = 1280 chunks, 5 per thread
    #pragma unroll
    for (int i = 0; i < 5; i++) {
        const int c = tid + 256 * i;
        const int row = c / 10, seg = c % 10;
        cpasync16(qb + (uint32_t)(row * PQH + seg * 4) * 4,
                  Qg + (size_t)(q0 + row) * 40 + seg * 4);
    }
    asm volatile("cp.async.commit_group;" ::: "memory");
    fill_kv(0, 0);

    float mL = -1e30f, mH = -1e30f, lL = 0.f, lH = 0.f;
    float of[10][4];
    #pragma unroll
    for (int i = 0; i < 10; i++)
        #pragma unroll
        for (int r = 0; r < 4; r++) of[i][r] = 0.f;

    int p = 0;
    for (int tt = 0; tt < CS; tt += 64, p ^= 1) {
        asm volatile("cp.async.wait_group 0;" ::: "memory");
        __syncthreads();

        if (tt + 64 < CS) fill_kv(tt + 64, p ^ 1);

        const uint32_t* Kb = Ks[p];
        const uint32_t* Vb = Vt[p];

        // ---- S = Q K^T : warp tile 16 x 64, 5 k16 steps; uint2 frag loads ----
        float sacc[8][4];
        #pragma unroll
        for (int in = 0; in < 8; in++)
            #pragma unroll
            for (int r = 0; r < 4; r++) sacc[in][r] = 0.f;

        #pragma unroll
        for (int ks = 0; ks < 5; ks++) {
            const int row = wid * 16 + g;
            const int off = ks * 8 + 2 * t;
            const uint2 qA = *reinterpret_cast<const uint2*>(Qs + row * PQH + off);       // (a0,a2)
            const uint2 qB = *reinterpret_cast<const uint2*>(Qs + (row + 8) * PQH + off); // (a1,a3)
            #pragma unroll
            for (int in = 0; in < 8; in++) {
                const int n = in * 8 + g;
                const uint2 kf = *reinterpret_cast<const uint2*>(Kb + n * PKH + off);     // (b0,b1)
                mma_f16(sacc[in], qA.x, qB.x, qA.y, qB.y, kf.x, kf.y);
            }
        }

        // ---- register-resident online softmax (exp2 domain) ----
        float mxL = -1e30f, mxH = -1e30f;
        #pragma unroll
        for (int in = 0; in < 8; in++) {
            mxL = fmaxf(mxL, fmaxf(sacc[in][0], sacc[in][1]));
            mxH = fmaxf(mxH, fmaxf(sacc[in][2], sacc[in][3]));
        }
        mxL = fmaxf(mxL, __shfl_xor_sync(0xffffffffu, mxL, 1));
        mxL = fmaxf(mxL, __shfl_xor_sync(0xffffffffu, mxL, 2));
        mxH = fmaxf(mxH, __shfl_xor_sync(0xffffffffu, mxH, 1));
        mxH = fmaxf(mxH, __shfl_xor_sync(0xffffffffu, mxH, 2));
        const float mnL = fmaxf(mL, mxL);
        const float mnH = fmaxf(mH, mxH);
        const float aL = exp2f(mL - mnL);
        const float aH = exp2f(mH - mnH);
        float rsL = 0.f, rsH = 0.f;
        #pragma unroll
        for (int in = 0; in < 8; in++) {
            sacc[in][0] = exp2f(sacc[in][0] - mnL);
            sacc[in][1] = exp2f(sacc[in][1] - mnL);
            sacc[in][2] = exp2f(sacc[in][2] - mnH);
            sacc[in][3] = exp2f(sacc[in][3] - mnH);
            rsL += sacc[in][0] + sacc[in][1];
            rsH += sacc[in][2] + sacc[in][3];
        }
        rsL += __shfl_xor_sync(0xffffffffu, rsL, 1);
        rsL += __shfl_xor_sync(0xffffffffu, rsL, 2);
        rsH += __shfl_xor_sync(0xffffffffu, rsH, 1);
        rsH += __shfl_xor_sync(0xffffffffu, rsH, 2);
        lL = lL * aL + rsL;  mL = mnL;
        lH = lH * aH + rsH;  mH = mnH;

        // ---- pack P into A-fragments ----
        uint32_t pa[4][4];
        #pragma unroll
        for (int ks = 0; ks < 4; ks++) {
            pa[ks][0] = f2h2(sacc[2 * ks][0],     sacc[2 * ks][1]);
            pa[ks][1] = f2h2(sacc[2 * ks][2],     sacc[2 * ks][3]);
            pa[ks][2] = f2h2(sacc[2 * ks + 1][0], sacc[2 * ks + 1][1]);
            pa[ks][3] = f2h2(sacc[2 * ks + 1][2], sacc[2 * ks + 1][3]);
        }

        // ---- O = O*alpha + P @ V : warp tile 16 x 80, 4 k16; uint2 loads ----
        #pragma unroll
        for (int in = 0; in < 10; in++) {
            of[in][0] *= aL; of[in][1] *= aL;
            of[in][2] *= aH; of[in][3] *= aH;
        }
        #pragma unroll
        for (int ks = 0; ks < 4; ks++) {
            const int off = ks * 8 + 2 * t;
            #pragma unroll
            for (int in = 0; in < 10; in++) {
                const int n = in * 8 + g;
                const uint2 vf = *reinterpret_cast<const uint2*>(Vb + n * PVH + off);
                mma_f16(of[in], pa[ks][0], pa[ks][1], pa[ks][2], pa[ks][3], vf.x, vf.y);
            }
        }
    }

    // ---- epilogue: normalize own rows, write g_ctxp fp16x2 (pperm) ----
    const int b = bh >> 4, h = bh & 15;
    const float invL = 1.f / lL;
    const float invH = 1.f / lH;
    const int rL = q0 + wid * 16 + g;
    const int rH = rL + 8;
    uint32_t* ctxL = g_ctxp + ((size_t)b * CS + rL) * KP;
    uint32_t* ctxH = g_ctxp + ((size_t)b * CS + rH) * KP;
    #pragma unroll
    for (int in = 0; in < 10; in++) {
        const int pairidx = h * 40 + in * 4 + t;
        const int ppos = pperm(pairidx);
        ctxL[ppos] = f2h2(of[in][0] * invL, of[in][1] * invL);
        ctxH[ppos] = f2h2(of[in][2] * invH, of[in][3] * invH);
    }
}

// ============================================================================
// launch
// ============================================================================
extern "C" void kernel_launch(void* const* d_in, const int* in_sizes, int n_in,
                              void* d_out, int out_size)
{
    const float* x        = (const float*)d_in[0];
    const float* rope_cos = (const float*)d_in[1];
    const float* rope_sin = (const float*)d_in[2];
    const float* Wqkv     = (const float*)d_in[3];
    const float* bqkv     = (const float*)d_in[4];
    const float* Wproj    = (const float*)d_in[5];
    const float* bproj    = (const float*)d_in[6];
    float* out            = (float*)d_out;

    // 0) merged prep: x + both weights -> fp16x2 permuted operands
    prep_all<<<PREP_TOTAL, 256>>>(x, Wqkv, Wproj);

    // 1) QKV projection -> g_q/g_k (fp32), g_vt (fp16, interleaved)
    cudaFuncSetAttribute(gemm_h2<0>, cudaFuncAttributeMaxDynamicSharedMemorySize, GEMM_SMEM);
    gemm_h2<0><<<dim3(CNQKV / 128, CM / 128), 128, GEMM_SMEM>>>(bqkv, nullptr, CNQKV);

    // 2) RoPE -> g_qp (fp16, scaled by SCALE*log2e, interleaved), g_kp
    {
        const int tot = CB * CH * CS * 20;
        rope_kernel<<<(tot + 255) / 256, 256>>>(rope_cos, rope_sin);
    }

    // 3) fused flash attention -> g_ctxp
    cudaFuncSetAttribute(attn_h2, cudaFuncAttributeMaxDynamicSharedMemorySize, ATTN_SMEM);
    attn_h2<<<dim3(CS / 128, CB * CH), 256, ATTN_SMEM>>>();

    // 4) output projection -> d_out
    cudaFuncSetAttribute(gemm_h2<1>, cudaFuncAttributeMaxDynamicSharedMemorySize, GEMM_SMEM);
    gemm_h2<1><<<dim3(CD / 128, CM / 128), 128, GEMM_SMEM>>>(bproj, out, CD);
}